// round 11
// baseline (speedup 1.0000x reference)
#include <cuda_runtime.h>
#include <cstdint>

// ---------------- problem constants ----------------
#define BATCH   16
#define SEQ     4096
#define CDIM    1024
#define NHEAD   16
#define DHEAD   64
#define LTOK    77
#define CENC    768
#define MQ      (BATCH*SEQ)      // 65536
#define MKV     (BATCH*LTOK)     // 1232

// ---------------- scratch ----------------
__device__ float g_q[(size_t)MQ * CDIM];
__device__ float g_attn[(size_t)MQ * CDIM];
__device__ float g_hs[(size_t)MQ * CDIM];
__device__ float g_k[(size_t)MKV * CDIM];
__device__ float g_v[(size_t)MKV * CDIM];
__device__ float g_wqt[CDIM * CDIM];
__device__ float g_wot[CDIM * CDIM];

__device__ __forceinline__ unsigned f2tf32(float x) {
    unsigned r;
    asm("cvt.rna.tf32.f32 %0, %1;" : "=r"(r) : "f"(x));
    return r;
}
__device__ __forceinline__ float rnd_tf32(float x) { return __uint_as_float(f2tf32(x)); }

__device__ __forceinline__ uint32_t smem_u32(const void* p) {
    uint32_t a;
    asm("{ .reg .u64 t; cvta.to.shared.u64 t, %1; cvt.u32.u64 %0, t; }" : "=r"(a) : "l"(p));
    return a;
}
#define CP16(dst, src) \
    asm volatile("cp.async.cg.shared.global [%0], [%1], 16;" :: "r"(dst), "l"(src) : "memory")
#define CP_COMMIT() asm volatile("cp.async.commit_group;" ::: "memory")
#define CP_WAIT2()  asm volatile("cp.async.wait_group 2;" ::: "memory")

#define LDSM4(r0, r1, r2, r3, addr) \
    asm volatile("ldmatrix.sync.aligned.m8n8.x4.shared.b16 {%0,%1,%2,%3}, [%4];" \
        : "=r"(r0), "=r"(r1), "=r"(r2), "=r"(r3) : "r"(addr))

__device__ __forceinline__ void mma8(float* d, unsigned a0, unsigned a1,
                                     unsigned a2, unsigned a3,
                                     unsigned b0, unsigned b1) {
    asm volatile(
        "mma.sync.aligned.m16n8k8.row.col.f32.tf32.tf32.f32 "
        "{%0,%1,%2,%3}, {%4,%5,%6,%7}, {%8,%9}, {%0,%1,%2,%3};"
        : "+f"(d[0]), "+f"(d[1]), "+f"(d[2]), "+f"(d[3])
        : "r"(a0), "r"(a1), "r"(a2), "r"(a3), "r"(b0), "r"(b1));
}

// ============================================================
// Pipelined TF32 GEMM v4: 256x128 CTA tile, warp tile 64x64.
// C[M,N] = A[M,K] @ BT[N,K]^T (+bias). A, BT pre-rounded tf32.
// KC=32, 4 stages (221KB smem, 1 CTA/SM), 256 thr, LDSM feeds.
// ============================================================
#define NSTAGE  4
#define KC      32
#define PR      36                            // row stride, words
#define A_BYTES (256 * PR * 4)                // 36864
#define B_BYTES (128 * PR * 4)                // 18432
#define STG_B   (A_BYTES + B_BYTES)           // 55296
#define PIPE_SMEM (NSTAGE * STG_B)            // 221184

__device__ __forceinline__ void pipe_issue(
    uint32_t sb, int s, const float* __restrict__ A, const float* __restrict__ BT,
    int m0, int n0, int kt, int K, int t)
{
    uint32_t base = sb + s * STG_B;
#pragma unroll
    for (int i = 0; i < 8; i++) {             // A: 256 rows x 8 chunks
        int f = t + i * 256;
        int r = f >> 3, c = f & 7;
        CP16(base + r * (PR * 4) + c * 16,
             A + (size_t)(m0 + r) * K + kt + c * 4);
    }
#pragma unroll
    for (int i = 0; i < 4; i++) {             // B: 128 rows x 8 chunks
        int f = t + i * 256;
        int r = f >> 3, c = f & 7;
        CP16(base + A_BYTES + r * (PR * 4) + c * 16,
             BT + (size_t)(n0 + r) * K + kt + c * 4);
    }
    CP_COMMIT();
}

__global__ void __launch_bounds__(256, 1) gemm_pipe(
    const float* __restrict__ A, const float* __restrict__ BT,
    float* __restrict__ C, int M, int K, int N,
    const float* __restrict__ bias)
{
    extern __shared__ char smem[];
    const uint32_t sb = smem_u32(smem);

    const int t    = threadIdx.x;
    const int m0   = blockIdx.y * 256;
    const int n0   = blockIdx.x * 128;
    const int lane = t & 31;
    const int wid  = t >> 5;
    const int wm   = (wid >> 1) * 64;         // 0,64,128,192
    const int wn   = (wid & 1) * 64;          // 0,64
    const int gid  = lane >> 2;
    const int tg   = lane & 3;
    const int nk   = K / KC;

    // per-thread ldmatrix addresses (byte offsets within a tile)
    const int a_thr = (((lane & 7) + ((lane >> 3) & 1) * 8) * PR + (lane >> 4) * 4) * 4;
    const int b_thr = (((lane & 7) + (lane >> 4) * 8) * PR + ((lane >> 3) & 1) * 4) * 4;

    float acc[4][8][4];
#pragma unroll
    for (int i = 0; i < 4; i++)
#pragma unroll
        for (int j = 0; j < 8; j++)
#pragma unroll
            for (int r = 0; r < 4; r++) acc[i][j][r] = 0.f;

#pragma unroll
    for (int s = 0; s < NSTAGE - 1; s++)
        pipe_issue(sb, s, A, BT, m0, n0, s * KC, K, t);

    int s = 0;
    for (int ki = 0; ki < nk; ki++) {
        CP_WAIT2();
        __syncthreads();

        if (ki + NSTAGE - 1 < nk) {
            int sn = s + NSTAGE - 1;
            if (sn >= NSTAGE) sn -= NSTAGE;
            pipe_issue(sb, sn, A, BT, m0, n0, (ki + NSTAGE - 1) * KC, K, t);
        } else {
            CP_COMMIT();
        }

        const uint32_t As_addr = sb + (uint32_t)s * STG_B;
        const uint32_t Bs_addr = As_addr + A_BYTES;

#pragma unroll
        for (int kk = 0; kk < KC; kk += 8) {
            unsigned a[4][4], bf[8][2];
#pragma unroll
            for (int mf = 0; mf < 4; mf++)
                LDSM4(a[mf][0], a[mf][1], a[mf][2], a[mf][3],
                      As_addr + (unsigned)(((wm + mf * 16) * PR + kk) * 4) + a_thr);
#pragma unroll
            for (int p = 0; p < 4; p++)
                LDSM4(bf[2 * p][0], bf[2 * p][1], bf[2 * p + 1][0], bf[2 * p + 1][1],
                      Bs_addr + (unsigned)(((wn + p * 16) * PR + kk) * 4) + b_thr);
#pragma unroll
            for (int mf = 0; mf < 4; mf++)
#pragma unroll
                for (int nf = 0; nf < 8; nf++)
                    mma8(acc[mf][nf], a[mf][0], a[mf][1], a[mf][2], a[mf][3],
                         bf[nf][0], bf[nf][1]);
        }
        if (++s == NSTAGE) s = 0;
    }

#pragma unroll
    for (int mf = 0; mf < 4; mf++) {
#pragma unroll
        for (int nf = 0; nf < 8; nf++) {
            int row = m0 + wm + mf * 16 + gid;
            int col = n0 + wn + nf * 8 + tg * 2;
            float b0 = 0.f, b1 = 0.f;
            if (bias) { b0 = bias[col]; b1 = bias[col + 1]; }
            *(float2*)(C + (size_t)row * N + col) =
                make_float2(acc[mf][nf][0] + b0, acc[mf][nf][1] + b1);
            *(float2*)(C + (size_t)(row + 8) * N + col) =
                make_float2(acc[mf][nf][2] + b0, acc[mf][nf][3] + b1);
        }
    }
}

// ---------------- tf32 pre-round / transpose passes ----------------
__global__ void cvt_tf32_kernel(const float4* __restrict__ in, float4* __restrict__ out, int n4) {
    int i = blockIdx.x * blockDim.x + threadIdx.x;
    if (i < n4) {
        float4 v = in[i];
        v.x = rnd_tf32(v.x); v.y = rnd_tf32(v.y);
        v.z = rnd_tf32(v.z); v.w = rnd_tf32(v.w);
        out[i] = v;
    }
}

__global__ void transpose_tf32_kernel(const float* __restrict__ W, float* __restrict__ WT,
                                      int K, int N) {
    __shared__ float tbuf[32][33];
    int k0 = blockIdx.y * 32, n0 = blockIdx.x * 32;
    int x = threadIdx.x, y = threadIdx.y;   // (32,8)
#pragma unroll
    for (int i = 0; i < 32; i += 8)
        tbuf[y + i][x] = W[(size_t)(k0 + y + i) * N + n0 + x];
    __syncthreads();
#pragma unroll
    for (int i = 0; i < 32; i += 8)
        WT[(size_t)(n0 + y + i) * K + k0 + x] = rnd_tf32(tbuf[x][y + i]);
}

// ============================================================
// Legacy single-buffer GEMM (small ragged K/V projections)
// ============================================================
#define PA 136
#define PB 136

__device__ __forceinline__ void gemm_body(
    const float* __restrict__ A, const float* __restrict__ B,
    float* __restrict__ C, int M, int K, int N,
    unsigned* As, unsigned* Bs)
{
    const int t    = threadIdx.x;
    const int m0   = blockIdx.y * 128;
    const int n0   = blockIdx.x * 128;
    const int lane = t & 31;
    const int wid  = t >> 5;
    const int wm   = (wid >> 2) * 64;
    const int wn   = (wid & 3) * 32;
    const int gid  = lane >> 2;
    const int tg   = lane & 3;

    float acc[4][4][4];
#pragma unroll
    for (int i = 0; i < 4; i++)
#pragma unroll
        for (int j = 0; j < 4; j++)
#pragma unroll
            for (int r = 0; r < 4; r++) acc[i][j][r] = 0.f;

    for (int kt = 0; kt < K; kt += 16) {
#pragma unroll
        for (int i = 0; i < 2; i++) {
            int f  = t + i * 256;
            int m  = f >> 2;
            int kq = (f & 3) << 2;
            float4 val = make_float4(0.f, 0.f, 0.f, 0.f);
            if (m0 + m < M)
                val = *(const float4*)(A + (size_t)(m0 + m) * K + kt + kq);
            As[(kq + 0) * PA + m] = f2tf32(val.x);
            As[(kq + 1) * PA + m] = f2tf32(val.y);
            As[(kq + 2) * PA + m] = f2tf32(val.z);
            As[(kq + 3) * PA + m] = f2tf32(val.w);
        }
#pragma unroll
        for (int i = 0; i < 2; i++) {
            int f  = t + i * 256;
            int kr = f >> 5;
            int nq = (f & 31) << 2;
            float4 val = *(const float4*)(B + (size_t)(kt + kr) * N + n0 + nq);
            uint4 w;
            w.x = f2tf32(val.x); w.y = f2tf32(val.y);
            w.z = f2tf32(val.z); w.w = f2tf32(val.w);
            *(uint4*)(&Bs[kr * PB + nq]) = w;
        }
        __syncthreads();

#pragma unroll
        for (int kk = 0; kk < 16; kk += 8) {
            unsigned a[4][4], bf[4][2];
#pragma unroll
            for (int mf = 0; mf < 4; mf++) {
                int mb = wm + mf * 16 + gid;
                a[mf][0] = As[(kk + tg) * PA + mb];
                a[mf][1] = As[(kk + tg) * PA + mb + 8];
                a[mf][2] = As[(kk + tg + 4) * PA + mb];
                a[mf][3] = As[(kk + tg + 4) * PA + mb + 8];
            }
#pragma unroll
            for (int nf = 0; nf < 4; nf++) {
                int nb = wn + nf * 8 + gid;
                bf[nf][0] = Bs[(kk + tg) * PB + nb];
                bf[nf][1] = Bs[(kk + tg + 4) * PB + nb];
            }
#pragma unroll
            for (int mf = 0; mf < 4; mf++)
#pragma unroll
                for (int nf = 0; nf < 4; nf++)
                    mma8(acc[mf][nf], a[mf][0], a[mf][1], a[mf][2], a[mf][3],
                         bf[nf][0], bf[nf][1]);
        }
        __syncthreads();
    }

#pragma unroll
    for (int mf = 0; mf < 4; mf++) {
#pragma unroll
        for (int nf = 0; nf < 4; nf++) {
            int row = m0 + wm + mf * 16 + gid;
            int col = n0 + wn + nf * 8 + tg * 2;
            if (row < M)
                *(float2*)(C + (size_t)row * N + col) =
                    make_float2(acc[mf][nf][0], acc[mf][nf][1]);
            if (row + 8 < M)
                *(float2*)(C + (size_t)(row + 8) * N + col) =
                    make_float2(acc[mf][nf][2], acc[mf][nf][3]);
        }
    }
}

__global__ void __launch_bounds__(256, 2) gemm_tf32_dual(
    const float* __restrict__ A,
    const float* __restrict__ B0, float* __restrict__ C0,
    const float* __restrict__ B1, float* __restrict__ C1,
    int M, int K, int N)
{
    __shared__ unsigned As[16 * PA];
    __shared__ unsigned Bs[16 * PB];
    const float* B = blockIdx.z ? B1 : B0;
    float*       C = blockIdx.z ? C1 : C0;
    gemm_body(A, B, C, M, K, N, As, Bs);
}

// ============================================================
// Tensor-core attention (R8, unchanged — ~380us measured)
// ============================================================
#define QS_OFF 0
#define KN_OFF 8704
#define VS_OFF 14144
#define ATTN_SMEM ((14144 + 80 * 72) * 4)   // 79616 bytes

__global__ void __launch_bounds__(256, 2) attn_mma(
    const float* __restrict__ q, const float* __restrict__ k,
    const float* __restrict__ v, float* __restrict__ o)
{
    extern __shared__ unsigned sm[];
    unsigned* Qs = sm + QS_OFF;
    unsigned* Kn = sm + KN_OFF;
    unsigned* Vs = sm + VS_OFF;

    const int bh = blockIdx.y;
    const int b  = bh >> 4;
    const int h  = bh & 15;
    const int s0 = blockIdx.x * 128;
    const int t  = threadIdx.x;

    const float* qbase = q + (size_t)(b * SEQ + s0) * CDIM + h * DHEAD;
    for (int f = t; f < 128 * 16; f += 256) {
        int r = f >> 4, c = (f & 15) * 4;
        float4 val = *(const float4*)(qbase + (size_t)r * CDIM + c);
        Qs[r * 68 + c + 0] = f2tf32(val.x);
        Qs[r * 68 + c + 1] = f2tf32(val.y);
        Qs[r * 68 + c + 2] = f2tf32(val.z);
        Qs[r * 68 + c + 3] = f2tf32(val.w);
    }
    const float* kbase = k + (size_t)(b * LTOK) * CDIM + h * DHEAD;
    for (int f = t; f < LTOK * 16; f += 256) {
        int j = f >> 4, c = (f & 15) * 4;
        float4 val = *(const float4*)(kbase + (size_t)j * CDIM + c);
        Kn[j * 68 + c + 0] = f2tf32(val.x);
        Kn[j * 68 + c + 1] = f2tf32(val.y);
        Kn[j * 68 + c + 2] = f2tf32(val.z);
        Kn[j * 68 + c + 3] = f2tf32(val.w);
    }
    if (t < 192) Kn[(77 + (t >> 6)) * 68 + (t & 63)] = 0;
    const float* vbase = v + (size_t)(b * LTOK) * CDIM + h * DHEAD;
    for (int f = t; f < LTOK * 16; f += 256) {
        int j = f >> 4, c = (f & 15) * 4;
        float4 val = *(const float4*)(vbase + (size_t)j * CDIM + c);
        Vs[j * 72 + c + 0] = f2tf32(val.x);
        Vs[j * 72 + c + 1] = f2tf32(val.y);
        Vs[j * 72 + c + 2] = f2tf32(val.z);
        Vs[j * 72 + c + 3] = f2tf32(val.w);
    }
    if (t < 192) Vs[(77 + (t >> 6)) * 72 + (t & 63)] = 0;
    __syncthreads();

    const int wid = t >> 5, lane = t & 31;
    const int gid = lane >> 2, tg = lane & 3;
    const int wm  = wid * 16;
    const int r0  = wm + gid, r1 = wm + gid + 8;

    float sacc[10][4];
#pragma unroll
    for (int nf = 0; nf < 10; nf++)
#pragma unroll
        for (int r = 0; r < 4; r++) sacc[nf][r] = 0.f;

#pragma unroll
    for (int kf = 0; kf < 8; kf++) {
        int kk = kf * 8;
        unsigned a0 = Qs[r0 * 68 + kk + tg];
        unsigned a1 = Qs[r1 * 68 + kk + tg];
        unsigned a2 = Qs[r0 * 68 + kk + tg + 4];
        unsigned a3 = Qs[r1 * 68 + kk + tg + 4];
#pragma unroll
        for (int nf = 0; nf < 10; nf++) {
            unsigned b0 = Kn[(nf * 8 + gid) * 68 + kk + tg];
            unsigned b1 = Kn[(nf * 8 + gid) * 68 + kk + tg + 4];
            mma8(sacc[nf], a0, a1, a2, a3, b0, b1);
        }
    }

    const float scale = 0.125f;
    float sum0 = 0.f, sum1 = 0.f;
#pragma unroll
    for (int nf = 0; nf < 10; nf++) {
        int col = nf * 8 + tg * 2;
        float e00 = (col     < LTOK) ? rnd_tf32(__expf(sacc[nf][0] * scale)) : 0.f;
        float e01 = (col + 1 < LTOK) ? rnd_tf32(__expf(sacc[nf][1] * scale)) : 0.f;
        float e10 = (col     < LTOK) ? rnd_tf32(__expf(sacc[nf][2] * scale)) : 0.f;
        float e11 = (col + 1 < LTOK) ? rnd_tf32(__expf(sacc[nf][3] * scale)) : 0.f;
        sum0 += e00 + e01;
        sum1 += e10 + e11;
        sacc[nf][0] = e00; sacc[nf][1] = e01;
        sacc[nf][2] = e10; sacc[nf][3] = e11;
    }
    sum0 += __shfl_xor_sync(0xffffffffu, sum0, 1);
    sum0 += __shfl_xor_sync(0xffffffffu, sum0, 2);
    sum1 += __shfl_xor_sync(0xffffffffu, sum1, 1);
    sum1 += __shfl_xor_sync(0xffffffffu, sum1, 2);
    const float inv0 = 1.0f / sum0;
    const float inv1 = 1.0f / sum1;

    float oacc[8][4];
#pragma unroll
    for (int nf = 0; nf < 8; nf++)
#pragma unroll
        for (int r = 0; r < 4; r++) oacc[nf][r] = 0.f;

    const int qbse = lane & 28;
    const int src1 = qbse | (tg >> 1);
    const int src2 = qbse | ((tg >> 1) + 2);
    const bool odd = tg & 1;

#pragma unroll
    for (int kf = 0; kf < 10; kf++) {
        float s00 = __shfl_sync(0xffffffffu, sacc[kf][0], src1);
        float s01 = __shfl_sync(0xffffffffu, sacc[kf][1], src1);
        float s10 = __shfl_sync(0xffffffffu, sacc[kf][2], src1);
        float s11 = __shfl_sync(0xffffffffu, sacc[kf][3], src1);
        float t00 = __shfl_sync(0xffffffffu, sacc[kf][0], src2);
        float t01 = __shfl_sync(0xffffffffu, sacc[kf][1], src2);
        float t10 = __shfl_sync(0xffffffffu, sacc[kf][2], src2);
        float t11 = __shfl_sync(0xffffffffu, sacc[kf][3], src2);
        unsigned a0 = __float_as_uint(odd ? s01 : s00);
        unsigned a1 = __float_as_uint(odd ? s11 : s10);
        unsigned a2 = __float_as_uint(odd ? t01 : t00);
        unsigned a3 = __float_as_uint(odd ? t11 : t10);
        int kk = kf * 8;
#pragma unroll
        for (int nf = 0; nf < 8; nf++) {
            unsigned b0 = Vs[(kk + tg) * 72 + nf * 8 + gid];
            unsigned b1 = Vs[(kk + tg + 4) * 72 + nf * 8 + gid];
            mma8(oacc[nf], a0, a1, a2, a3, b0, b1);
        }
    }

    float* ob0 = o + (size_t)(b * SEQ + s0 + r0) * CDIM + h * DHEAD;
    float* ob1 = o + (size_t)(b * SEQ + s0 + r1) * CDIM + h * DHEAD;
#pragma unroll
    for (int nf = 0; nf < 8; nf++) {
        int col = nf * 8 + tg * 2;
        *(float2*)(ob0 + col) = make_float2(rnd_tf32(oacc[nf][0] * inv0),
                                            rnd_tf32(oacc[nf][1] * inv0));
        *(float2*)(ob1 + col) = make_float2(rnd_tf32(oacc[nf][2] * inv1),
                                            rnd_tf32(oacc[nf][3] * inv1));
    }
}

// ============================================================
// launch
// ============================================================
extern "C" void kernel_launch(void* const* d_in, const int* in_sizes, int n_in,
                              void* d_out, int out_size)
{
    const float* hs  = (const float*)d_in[0];
    const float* enc = (const float*)d_in[1];
    const float* Wq  = (const float*)d_in[2];
    const float* Wk  = (const float*)d_in[3];
    const float* Wv  = (const float*)d_in[4];
    const float* Wo  = (const float*)d_in[5];
    const float* bo  = (const float*)d_in[6];
    float* out = (float*)d_out;
    (void)in_sizes; (void)n_in; (void)out_size;

    float *qb, *kb, *vb, *ab, *hsb, *wqt, *wot;
    cudaGetSymbolAddress((void**)&qb,  g_q);
    cudaGetSymbolAddress((void**)&kb,  g_k);
    cudaGetSymbolAddress((void**)&vb,  g_v);
    cudaGetSymbolAddress((void**)&ab,  g_attn);
    cudaGetSymbolAddress((void**)&hsb, g_hs);
    cudaGetSymbolAddress((void**)&wqt, g_wqt);
    cudaGetSymbolAddress((void**)&wot, g_wot);

    // pre-round A operand; round+transpose weights for B operand
    cvt_tf32_kernel<<<(MQ * CDIM / 4 + 255) / 256, 256>>>((const float4*)hs, (float4*)hsb, MQ * CDIM / 4);
    transpose_tf32_kernel<<<dim3(CDIM / 32, CDIM / 32), dim3(32, 8)>>>(Wq, wqt, CDIM, CDIM);
    transpose_tf32_kernel<<<dim3(CDIM / 32, CDIM / 32), dim3(32, 8)>>>(Wo, wot, CDIM, CDIM);

    cudaFuncSetAttribute(gemm_pipe, cudaFuncAttributeMaxDynamicSharedMemorySize, PIPE_SMEM);

    // q = hs @ Wq  (pipelined, 256x128 tile)
    gemm_pipe<<<dim3(CDIM / 128, MQ / 256), 256, PIPE_SMEM>>>(hsb, wqt, qb, MQ, CDIM, CDIM, nullptr);

    // k,v = enc @ {Wk,Wv}
    gemm_tf32_dual<<<dim3(CDIM / 128, (MKV + 127) / 128, 2), 256>>>(
        enc, Wk, kb, Wv, vb, MKV, CENC, CDIM);

    // tensor-core attention
    cudaFuncSetAttribute(attn_mma, cudaFuncAttributeMaxDynamicSharedMemorySize, ATTN_SMEM);
    attn_mma<<<dim3(SEQ / 128, BATCH * NHEAD), 256, ATTN_SMEM>>>(qb, kb, vb, ab);

    // out = attn @ Wo + bo  (pipelined, 256x128 tile)
    gemm_pipe<<<dim3(CDIM / 128, MQ / 256), 256, PIPE_SMEM>>>(ab, wot, out, MQ, CDIM, CDIM, bo);
}

// round 12
// speedup vs baseline: 1.1078x; 1.1078x over previous
#include <cuda_runtime.h>
#include <cstdint>

// ---------------- problem constants ----------------
#define BATCH   16
#define SEQ     4096
#define CDIM    1024
#define NHEAD   16
#define DHEAD   64
#define LTOK    77
#define CENC    768
#define MQ      (BATCH*SEQ)      // 65536
#define MKV     (BATCH*LTOK)     // 1232

// ---------------- scratch ----------------
__device__ float g_q[(size_t)MQ * CDIM];
__device__ float g_attn[(size_t)MQ * CDIM];
__device__ float g_hs[(size_t)MQ * CDIM];
__device__ float g_k[(size_t)MKV * CDIM];
__device__ float g_v[(size_t)MKV * CDIM];
__device__ float g_wqt[CDIM * CDIM];
__device__ float g_wot[CDIM * CDIM];

__device__ __forceinline__ unsigned f2tf32(float x) {
    unsigned r;
    asm("cvt.rna.tf32.f32 %0, %1;" : "=r"(r) : "f"(x));
    return r;
}
__device__ __forceinline__ float rnd_tf32(float x) { return __uint_as_float(f2tf32(x)); }

__device__ __forceinline__ uint32_t smem_u32(const void* p) {
    uint32_t a;
    asm("{ .reg .u64 t; cvta.to.shared.u64 t, %1; cvt.u32.u64 %0, t; }" : "=r"(a) : "l"(p));
    return a;
}
#define CP16(dst, src) \
    asm volatile("cp.async.cg.shared.global [%0], [%1], 16;" :: "r"(dst), "l"(src) : "memory")
#define CP_COMMIT() asm volatile("cp.async.commit_group;" ::: "memory")
#define CP_WAIT1()  asm volatile("cp.async.wait_group 1;" ::: "memory")

#define LDSM4(r0, r1, r2, r3, addr) \
    asm volatile("ldmatrix.sync.aligned.m8n8.x4.shared.b16 {%0,%1,%2,%3}, [%4];" \
        : "=r"(r0), "=r"(r1), "=r"(r2), "=r"(r3) : "r"(addr))

__device__ __forceinline__ void mma8(float* d, unsigned a0, unsigned a1,
                                     unsigned a2, unsigned a3,
                                     unsigned b0, unsigned b1) {
    asm volatile(
        "mma.sync.aligned.m16n8k8.row.col.f32.tf32.tf32.f32 "
        "{%0,%1,%2,%3}, {%4,%5,%6,%7}, {%8,%9}, {%0,%1,%2,%3};"
        : "+f"(d[0]), "+f"(d[1]), "+f"(d[2]), "+f"(d[3])
        : "r"(a0), "r"(a1), "r"(a2), "r"(a3), "r"(b0), "r"(b1));
}

// ============================================================
// Pipelined TF32 GEMM (R10 config: 128x128, KC=32, 3 stages,
// 2 CTAs/SM, LDSM feeds) + R12 scheduling:
//  - per-warp-pair kk-group rotation (desync LDSM/mma phases)
//  - prefetch issued after first fragment loads
// C[M,N] = A[M,K] @ BT[N,K]^T (+bias), operands pre-rounded tf32.
// ============================================================
#define NSTAGE  3
#define KC      32
#define PR      36                           // row stride, words
#define T_BYTES (128 * PR * 4)               // 18432 per tile
#define STG_B   (2 * T_BYTES)                // 36864
#define PIPE_SMEM (NSTAGE * STG_B)           // 110592

__device__ __forceinline__ void pipe_issue(
    uint32_t sb, int s, const float* __restrict__ A, const float* __restrict__ BT,
    int m0, int n0, int kt, int K, int t)
{
    uint32_t base = sb + s * STG_B;
#pragma unroll
    for (int i = 0; i < 4; i++) {
        int f = t + i * 256;
        int r = f >> 3, c = f & 7;
        CP16(base + r * (PR * 4) + c * 16,
             A + (size_t)(m0 + r) * K + kt + c * 4);
    }
#pragma unroll
    for (int i = 0; i < 4; i++) {
        int f = t + i * 256;
        int r = f >> 3, c = f & 7;
        CP16(base + T_BYTES + r * (PR * 4) + c * 16,
             BT + (size_t)(n0 + r) * K + kt + c * 4);
    }
    CP_COMMIT();
}

__global__ void __launch_bounds__(256, 2) gemm_pipe(
    const float* __restrict__ A, const float* __restrict__ BT,
    float* __restrict__ C, int M, int K, int N,
    const float* __restrict__ bias)
{
    extern __shared__ char smem[];
    const uint32_t sb = smem_u32(smem);

    const int t    = threadIdx.x;
    const int m0   = blockIdx.y * 128;
    const int n0   = blockIdx.x * 128;
    const int lane = t & 31;
    const int wid  = t >> 5;
    const int wm   = (wid >> 2) * 64;
    const int wn   = (wid & 3) * 32;
    const int gid  = lane >> 2;
    const int tg   = lane & 3;
    const int nk   = K / KC;
    const int rot  = (wid >> 2) << 1;        // 0 or 2: stagger warp pairs

    // per-thread ldmatrix row addresses (byte offsets within a tile)
    const int a_thr = (((lane & 7) + ((lane >> 3) & 1) * 8) * PR + (lane >> 4) * 4) * 4;
    const int b_thr = (((lane & 7) + (lane >> 4) * 8) * PR + ((lane >> 3) & 1) * 4) * 4;

    float acc[4][4][4];
#pragma unroll
    for (int i = 0; i < 4; i++)
#pragma unroll
        for (int j = 0; j < 4; j++)
#pragma unroll
            for (int r = 0; r < 4; r++) acc[i][j][r] = 0.f;

#pragma unroll
    for (int s = 0; s < NSTAGE - 1; s++)
        pipe_issue(sb, s, A, BT, m0, n0, s * KC, K, t);

    int s = 0;
    for (int ki = 0; ki < nk; ki++) {
        CP_WAIT1();
        __syncthreads();

        const uint32_t As_addr = sb + (uint32_t)s * STG_B;
        const uint32_t Bs_addr = As_addr + T_BYTES;
        const bool do_pf = (ki + NSTAGE - 1 < nk);
        int sn = s + NSTAGE - 1;
        if (sn >= NSTAGE) sn -= NSTAGE;

#pragma unroll
        for (int gg = 0; gg < 4; gg++) {
            const int kk = ((gg + rot) & 3) * 8;
            unsigned a[4][4], bf[4][2];
#pragma unroll
            for (int mf = 0; mf < 4; mf++)
                LDSM4(a[mf][0], a[mf][1], a[mf][2], a[mf][3],
                      As_addr + (unsigned)(((wm + mf * 16) * PR + kk) * 4) + a_thr);
#pragma unroll
            for (int p = 0; p < 2; p++)
                LDSM4(bf[2 * p][0], bf[2 * p][1], bf[2 * p + 1][0], bf[2 * p + 1][1],
                      Bs_addr + (unsigned)(((wn + p * 16) * PR + kk) * 4) + b_thr);

            if (gg == 0) {
                // prefetch overlaps the tensor phase instead of preceding it
                if (do_pf)
                    pipe_issue(sb, sn, A, BT, m0, n0, (ki + NSTAGE - 1) * KC, K, t);
                else
                    CP_COMMIT();
            }

#pragma unroll
            for (int mf = 0; mf < 4; mf++)
#pragma unroll
                for (int nf = 0; nf < 4; nf++)
                    mma8(acc[mf][nf], a[mf][0], a[mf][1], a[mf][2], a[mf][3],
                         bf[nf][0], bf[nf][1]);
        }
        if (++s == NSTAGE) s = 0;
    }

#pragma unroll
    for (int mf = 0; mf < 4; mf++) {
#pragma unroll
        for (int nf = 0; nf < 4; nf++) {
            int row = m0 + wm + mf * 16 + gid;
            int col = n0 + wn + nf * 8 + tg * 2;
            float b0 = 0.f, b1 = 0.f;
            if (bias) { b0 = bias[col]; b1 = bias[col + 1]; }
            *(float2*)(C + (size_t)row * N + col) =
                make_float2(acc[mf][nf][0] + b0, acc[mf][nf][1] + b1);
            *(float2*)(C + (size_t)(row + 8) * N + col) =
                make_float2(acc[mf][nf][2] + b0, acc[mf][nf][3] + b1);
        }
    }
}

// ---------------- tf32 pre-round / transpose passes ----------------
__global__ void cvt_tf32_kernel(const float4* __restrict__ in, float4* __restrict__ out, int n4) {
    int i = blockIdx.x * blockDim.x + threadIdx.x;
    if (i < n4) {
        float4 v = in[i];
        v.x = rnd_tf32(v.x); v.y = rnd_tf32(v.y);
        v.z = rnd_tf32(v.z); v.w = rnd_tf32(v.w);
        out[i] = v;
    }
}

__global__ void transpose_tf32_kernel(const float* __restrict__ W, float* __restrict__ WT,
                                      int K, int N) {
    __shared__ float tbuf[32][33];
    int k0 = blockIdx.y * 32, n0 = blockIdx.x * 32;
    int x = threadIdx.x, y = threadIdx.y;   // (32,8)
#pragma unroll
    for (int i = 0; i < 32; i += 8)
        tbuf[y + i][x] = W[(size_t)(k0 + y + i) * N + n0 + x];
    __syncthreads();
#pragma unroll
    for (int i = 0; i < 32; i += 8)
        WT[(size_t)(n0 + y + i) * K + k0 + x] = rnd_tf32(tbuf[x][y + i]);
}

// ============================================================
// Legacy single-buffer GEMM (small ragged K/V projections)
// ============================================================
#define PA 136
#define PB 136

__device__ __forceinline__ void gemm_body(
    const float* __restrict__ A, const float* __restrict__ B,
    float* __restrict__ C, int M, int K, int N,
    unsigned* As, unsigned* Bs)
{
    const int t    = threadIdx.x;
    const int m0   = blockIdx.y * 128;
    const int n0   = blockIdx.x * 128;
    const int lane = t & 31;
    const int wid  = t >> 5;
    const int wm   = (wid >> 2) * 64;
    const int wn   = (wid & 3) * 32;
    const int gid  = lane >> 2;
    const int tg   = lane & 3;

    float acc[4][4][4];
#pragma unroll
    for (int i = 0; i < 4; i++)
#pragma unroll
        for (int j = 0; j < 4; j++)
#pragma unroll
            for (int r = 0; r < 4; r++) acc[i][j][r] = 0.f;

    for (int kt = 0; kt < K; kt += 16) {
#pragma unroll
        for (int i = 0; i < 2; i++) {
            int f  = t + i * 256;
            int m  = f >> 2;
            int kq = (f & 3) << 2;
            float4 val = make_float4(0.f, 0.f, 0.f, 0.f);
            if (m0 + m < M)
                val = *(const float4*)(A + (size_t)(m0 + m) * K + kt + kq);
            As[(kq + 0) * PA + m] = f2tf32(val.x);
            As[(kq + 1) * PA + m] = f2tf32(val.y);
            As[(kq + 2) * PA + m] = f2tf32(val.z);
            As[(kq + 3) * PA + m] = f2tf32(val.w);
        }
#pragma unroll
        for (int i = 0; i < 2; i++) {
            int f  = t + i * 256;
            int kr = f >> 5;
            int nq = (f & 31) << 2;
            float4 val = *(const float4*)(B + (size_t)(kt + kr) * N + n0 + nq);
            uint4 w;
            w.x = f2tf32(val.x); w.y = f2tf32(val.y);
            w.z = f2tf32(val.z); w.w = f2tf32(val.w);
            *(uint4*)(&Bs[kr * PB + nq]) = w;
        }
        __syncthreads();

#pragma unroll
        for (int kk = 0; kk < 16; kk += 8) {
            unsigned a[4][4], bf[4][2];
#pragma unroll
            for (int mf = 0; mf < 4; mf++) {
                int mb = wm + mf * 16 + gid;
                a[mf][0] = As[(kk + tg) * PA + mb];
                a[mf][1] = As[(kk + tg) * PA + mb + 8];
                a[mf][2] = As[(kk + tg + 4) * PA + mb];
                a[mf][3] = As[(kk + tg + 4) * PA + mb + 8];
            }
#pragma unroll
            for (int nf = 0; nf < 4; nf++) {
                int nb = wn + nf * 8 + gid;
                bf[nf][0] = Bs[(kk + tg) * PB + nb];
                bf[nf][1] = Bs[(kk + tg + 4) * PB + nb];
            }
#pragma unroll
            for (int mf = 0; mf < 4; mf++)
#pragma unroll
                for (int nf = 0; nf < 4; nf++)
                    mma8(acc[mf][nf], a[mf][0], a[mf][1], a[mf][2], a[mf][3],
                         bf[nf][0], bf[nf][1]);
        }
        __syncthreads();
    }

#pragma unroll
    for (int mf = 0; mf < 4; mf++) {
#pragma unroll
        for (int nf = 0; nf < 4; nf++) {
            int row = m0 + wm + mf * 16 + gid;
            int col = n0 + wn + nf * 8 + tg * 2;
            if (row < M)
                *(float2*)(C + (size_t)row * N + col) =
                    make_float2(acc[mf][nf][0], acc[mf][nf][1]);
            if (row + 8 < M)
                *(float2*)(C + (size_t)(row + 8) * N + col) =
                    make_float2(acc[mf][nf][2], acc[mf][nf][3]);
        }
    }
}

__global__ void __launch_bounds__(256, 2) gemm_tf32_dual(
    const float* __restrict__ A,
    const float* __restrict__ B0, float* __restrict__ C0,
    const float* __restrict__ B1, float* __restrict__ C1,
    int M, int K, int N)
{
    __shared__ unsigned As[16 * PA];
    __shared__ unsigned Bs[16 * PB];
    const float* B = blockIdx.z ? B1 : B0;
    float*       C = blockIdx.z ? C1 : C0;
    gemm_body(A, B, C, M, K, N, As, Bs);
}

// ============================================================
// Tensor-core attention (R8, unchanged — ~380us measured)
// ============================================================
#define QS_OFF 0
#define KN_OFF 8704
#define VS_OFF 14144
#define ATTN_SMEM ((14144 + 80 * 72) * 4)   // 79616 bytes

__global__ void __launch_bounds__(256, 2) attn_mma(
    const float* __restrict__ q, const float* __restrict__ k,
    const float* __restrict__ v, float* __restrict__ o)
{
    extern __shared__ unsigned sm[];
    unsigned* Qs = sm + QS_OFF;
    unsigned* Kn = sm + KN_OFF;
    unsigned* Vs = sm + VS_OFF;

    const int bh = blockIdx.y;
    const int b  = bh >> 4;
    const int h  = bh & 15;
    const int s0 = blockIdx.x * 128;
    const int t  = threadIdx.x;

    const float* qbase = q + (size_t)(b * SEQ + s0) * CDIM + h * DHEAD;
    for (int f = t; f < 128 * 16; f += 256) {
        int r = f >> 4, c = (f & 15) * 4;
        float4 val = *(const float4*)(qbase + (size_t)r * CDIM + c);
        Qs[r * 68 + c + 0] = f2tf32(val.x);
        Qs[r * 68 + c + 1] = f2tf32(val.y);
        Qs[r * 68 + c + 2] = f2tf32(val.z);
        Qs[r * 68 + c + 3] = f2tf32(val.w);
    }
    const float* kbase = k + (size_t)(b * LTOK) * CDIM + h * DHEAD;
    for (int f = t; f < LTOK * 16; f += 256) {
        int j = f >> 4, c = (f & 15) * 4;
        float4 val = *(const float4*)(kbase + (size_t)j * CDIM + c);
        Kn[j * 68 + c + 0] = f2tf32(val.x);
        Kn[j * 68 + c + 1] = f2tf32(val.y);
        Kn[j * 68 + c + 2] = f2tf32(val.z);
        Kn[j * 68 + c + 3] = f2tf32(val.w);
    }
    if (t < 192) Kn[(77 + (t >> 6)) * 68 + (t & 63)] = 0;
    const float* vbase = v + (size_t)(b * LTOK) * CDIM + h * DHEAD;
    for (int f = t; f < LTOK * 16; f += 256) {
        int j = f >> 4, c = (f & 15) * 4;
        float4 val = *(const float4*)(vbase + (size_t)j * CDIM + c);
        Vs[j * 72 + c + 0] = f2tf32(val.x);
        Vs[j * 72 + c + 1] = f2tf32(val.y);
        Vs[j * 72 + c + 2] = f2tf32(val.z);
        Vs[j * 72 + c + 3] = f2tf32(val.w);
    }
    if (t < 192) Vs[(77 + (t >> 6)) * 72 + (t & 63)] = 0;
    __syncthreads();

    const int wid = t >> 5, lane = t & 31;
    const int gid = lane >> 2, tg = lane & 3;
    const int wm  = wid * 16;
    const int r0  = wm + gid, r1 = wm + gid + 8;

    float sacc[10][4];
#pragma unroll
    for (int nf = 0; nf < 10; nf++)
#pragma unroll
        for (int r = 0; r < 4; r++) sacc[nf][r] = 0.f;

#pragma unroll
    for (int kf = 0; kf < 8; kf++) {
        int kk = kf * 8;
        unsigned a0 = Qs[r0 * 68 + kk + tg];
        unsigned a1 = Qs[r1 * 68 + kk + tg];
        unsigned a2 = Qs[r0 * 68 + kk + tg + 4];
        unsigned a3 = Qs[r1 * 68 + kk + tg + 4];
#pragma unroll
        for (int nf = 0; nf < 10; nf++) {
            unsigned b0 = Kn[(nf * 8 + gid) * 68 + kk + tg];
            unsigned b1 = Kn[(nf * 8 + gid) * 68 + kk + tg + 4];
            mma8(sacc[nf], a0, a1, a2, a3, b0, b1);
        }
    }

    const float scale = 0.125f;
    float sum0 = 0.f, sum1 = 0.f;
#pragma unroll
    for (int nf = 0; nf < 10; nf++) {
        int col = nf * 8 + tg * 2;
        float e00 = (col     < LTOK) ? rnd_tf32(__expf(sacc[nf][0] * scale)) : 0.f;
        float e01 = (col + 1 < LTOK) ? rnd_tf32(__expf(sacc[nf][1] * scale)) : 0.f;
        float e10 = (col     < LTOK) ? rnd_tf32(__expf(sacc[nf][2] * scale)) : 0.f;
        float e11 = (col + 1 < LTOK) ? rnd_tf32(__expf(sacc[nf][3] * scale)) : 0.f;
        sum0 += e00 + e01;
        sum1 += e10 + e11;
        sacc[nf][0] = e00; sacc[nf][1] = e01;
        sacc[nf][2] = e10; sacc[nf][3] = e11;
    }
    sum0 += __shfl_xor_sync(0xffffffffu, sum0, 1);
    sum0 += __shfl_xor_sync(0xffffffffu, sum0, 2);
    sum1 += __shfl_xor_sync(0xffffffffu, sum1, 1);
    sum1 += __shfl_xor_sync(0xffffffffu, sum1, 2);
    const float inv0 = 1.0f / sum0;
    const float inv1 = 1.0f / sum1;

    float oacc[8][4];
#pragma unroll
    for (int nf = 0; nf < 8; nf++)
#pragma unroll
        for (int r = 0; r < 4; r++) oacc[nf][r] = 0.f;

    const int qbse = lane & 28;
    const int src1 = qbse | (tg >> 1);
    const int src2 = qbse | ((tg >> 1) + 2);
    const bool odd = tg & 1;

#pragma unroll
    for (int kf = 0; kf < 10; kf++) {
        float s00 = __shfl_sync(0xffffffffu, sacc[kf][0], src1);
        float s01 = __shfl_sync(0xffffffffu, sacc[kf][1], src1);
        float s10 = __shfl_sync(0xffffffffu, sacc[kf][2], src1);
        float s11 = __shfl_sync(0xffffffffu, sacc[kf][3], src1);
        float t00 = __shfl_sync(0xffffffffu, sacc[kf][0], src2);
        float t01 = __shfl_sync(0xffffffffu, sacc[kf][1], src2);
        float t10 = __shfl_sync(0xffffffffu, sacc[kf][2], src2);
        float t11 = __shfl_sync(0xffffffffu, sacc[kf][3], src2);
        unsigned a0 = __float_as_uint(odd ? s01 : s00);
        unsigned a1 = __float_as_uint(odd ? s11 : s10);
        unsigned a2 = __float_as_uint(odd ? t01 : t00);
        unsigned a3 = __float_as_uint(odd ? t11 : t10);
        int kk = kf * 8;
#pragma unroll
        for (int nf = 0; nf < 8; nf++) {
            unsigned b0 = Vs[(kk + tg) * 72 + nf * 8 + gid];
            unsigned b1 = Vs[(kk + tg + 4) * 72 + nf * 8 + gid];
            mma8(oacc[nf], a0, a1, a2, a3, b0, b1);
        }
    }

    float* ob0 = o + (size_t)(b * SEQ + s0 + r0) * CDIM + h * DHEAD;
    float* ob1 = o + (size_t)(b * SEQ + s0 + r1) * CDIM + h * DHEAD;
#pragma unroll
    for (int nf = 0; nf < 8; nf++) {
        int col = nf * 8 + tg * 2;
        *(float2*)(ob0 + col) = make_float2(rnd_tf32(oacc[nf][0] * inv0),
                                            rnd_tf32(oacc[nf][1] * inv0));
        *(float2*)(ob1 + col) = make_float2(rnd_tf32(oacc[nf][2] * inv1),
                                            rnd_tf32(oacc[nf][3] * inv1));
    }
}

// ============================================================
// launch
// ============================================================
extern "C" void kernel_launch(void* const* d_in, const int* in_sizes, int n_in,
                              void* d_out, int out_size)
{
    const float* hs  = (const float*)d_in[0];
    const float* enc = (const float*)d_in[1];
    const float* Wq  = (const float*)d_in[2];
    const float* Wk  = (const float*)d_in[3];
    const float* Wv  = (const float*)d_in[4];
    const float* Wo  = (const float*)d_in[5];
    const float* bo  = (const float*)d_in[6];
    float* out = (float*)d_out;
    (void)in_sizes; (void)n_in; (void)out_size;

    float *qb, *kb, *vb, *ab, *hsb, *wqt, *wot;
    cudaGetSymbolAddress((void**)&qb,  g_q);
    cudaGetSymbolAddress((void**)&kb,  g_k);
    cudaGetSymbolAddress((void**)&vb,  g_v);
    cudaGetSymbolAddress((void**)&ab,  g_attn);
    cudaGetSymbolAddress((void**)&hsb, g_hs);
    cudaGetSymbolAddress((void**)&wqt, g_wqt);
    cudaGetSymbolAddress((void**)&wot, g_wot);

    // pre-round A operand; round+transpose weights for B operand
    cvt_tf32_kernel<<<(MQ * CDIM / 4 + 255) / 256, 256>>>((const float4*)hs, (float4*)hsb, MQ * CDIM / 4);
    transpose_tf32_kernel<<<dim3(CDIM / 32, CDIM / 32), dim3(32, 8)>>>(Wq, wqt, CDIM, CDIM);
    transpose_tf32_kernel<<<dim3(CDIM / 32, CDIM / 32), dim3(32, 8)>>>(Wo, wot, CDIM, CDIM);

    cudaFuncSetAttribute(gemm_pipe, cudaFuncAttributeMaxDynamicSharedMemorySize, PIPE_SMEM);

    // q = hs @ Wq
    gemm_pipe<<<dim3(CDIM / 128, MQ / 128), 256, PIPE_SMEM>>>(hsb, wqt, qb, MQ, CDIM, CDIM, nullptr);

    // k,v = enc @ {Wk,Wv}
    gemm_tf32_dual<<<dim3(CDIM / 128, (MKV + 127) / 128, 2), 256>>>(
        enc, Wk, kb, Wv, vb, MKV, CENC, CDIM);

    // tensor-core attention
    cudaFuncSetAttribute(attn_mma, cudaFuncAttributeMaxDynamicSharedMemorySize, ATTN_SMEM);
    attn_mma<<<dim3(SEQ / 128, BATCH * NHEAD), 256, ATTN_SMEM>>>(qb, kb, vb, ab);

    // out = attn @ Wo + bo
    gemm_pipe<<<dim3(CDIM / 128, MQ / 128), 256, PIPE_SMEM>>>(ab, wot, out, MQ, CDIM, CDIM, bo);
}

// round 13
// speedup vs baseline: 1.1692x; 1.0554x over previous
#include <cuda_runtime.h>
#include <cstdint>

// ---------------- problem constants ----------------
#define BATCH   16
#define SEQ     4096
#define CDIM    1024
#define NHEAD   16
#define DHEAD   64
#define LTOK    77
#define CENC    768
#define MQ      (BATCH*SEQ)      // 65536
#define MKV     (BATCH*LTOK)     // 1232

// ---------------- scratch ----------------
__device__ float g_q[(size_t)MQ * CDIM];
__device__ float g_attn[(size_t)MQ * CDIM];
__device__ float g_hs[(size_t)MQ * CDIM];
__device__ float g_k[(size_t)MKV * CDIM];
__device__ float g_v[(size_t)MKV * CDIM];
__device__ float g_wqt[CDIM * CDIM];
__device__ float g_wot[CDIM * CDIM];

__device__ __forceinline__ unsigned f2tf32(float x) {
    unsigned r;
    asm("cvt.rna.tf32.f32 %0, %1;" : "=r"(r) : "f"(x));
    return r;
}
__device__ __forceinline__ float rnd_tf32(float x) { return __uint_as_float(f2tf32(x)); }

__device__ __forceinline__ uint32_t smem_u32(const void* p) {
    uint32_t a;
    asm("{ .reg .u64 t; cvta.to.shared.u64 t, %1; cvt.u32.u64 %0, t; }" : "=r"(a) : "l"(p));
    return a;
}
#define CP16(dst, src) \
    asm volatile("cp.async.cg.shared.global [%0], [%1], 16;" :: "r"(dst), "l"(src) : "memory")
#define CP_COMMIT() asm volatile("cp.async.commit_group;" ::: "memory")
#define CP_WAIT1()  asm volatile("cp.async.wait_group 1;" ::: "memory")
#define CP_WAIT0()  asm volatile("cp.async.wait_group 0;" ::: "memory")

#define LDSM4(r0, r1, r2, r3, addr) \
    asm volatile("ldmatrix.sync.aligned.m8n8.x4.shared.b16 {%0,%1,%2,%3}, [%4];" \
        : "=r"(r0), "=r"(r1), "=r"(r2), "=r"(r3) : "r"(addr))

__device__ __forceinline__ void mma8(float* d, unsigned a0, unsigned a1,
                                     unsigned a2, unsigned a3,
                                     unsigned b0, unsigned b1) {
    asm volatile(
        "mma.sync.aligned.m16n8k8.row.col.f32.tf32.tf32.f32 "
        "{%0,%1,%2,%3}, {%4,%5,%6,%7}, {%8,%9}, {%0,%1,%2,%3};"
        : "+f"(d[0]), "+f"(d[1]), "+f"(d[2]), "+f"(d[3])
        : "r"(a0), "r"(a1), "r"(a2), "r"(a3), "r"(b0), "r"(b1));
}

// ============================================================
// Pipelined TF32 GEMM (R12 config, + optional rounded output).
// C[M,N] = A[M,K] @ BT[N,K]^T (+bias), operands pre-rounded tf32.
// ============================================================
#define NSTAGE  3
#define KC      32
#define PR      36
#define T_BYTES (128 * PR * 4)
#define STG_B   (2 * T_BYTES)
#define PIPE_SMEM (NSTAGE * STG_B)

__device__ __forceinline__ void pipe_issue(
    uint32_t sb, int s, const float* __restrict__ A, const float* __restrict__ BT,
    int m0, int n0, int kt, int K, int t)
{
    uint32_t base = sb + s * STG_B;
#pragma unroll
    for (int i = 0; i < 4; i++) {
        int f = t + i * 256;
        int r = f >> 3, c = f & 7;
        CP16(base + r * (PR * 4) + c * 16,
             A + (size_t)(m0 + r) * K + kt + c * 4);
    }
#pragma unroll
    for (int i = 0; i < 4; i++) {
        int f = t + i * 256;
        int r = f >> 3, c = f & 7;
        CP16(base + T_BYTES + r * (PR * 4) + c * 16,
             BT + (size_t)(n0 + r) * K + kt + c * 4);
    }
    CP_COMMIT();
}

__global__ void __launch_bounds__(256, 2) gemm_pipe(
    const float* __restrict__ A, const float* __restrict__ BT,
    float* __restrict__ C, int M, int K, int N,
    const float* __restrict__ bias, int rnd_out)
{
    extern __shared__ char smem[];
    const uint32_t sb = smem_u32(smem);

    const int t    = threadIdx.x;
    const int m0   = blockIdx.y * 128;
    const int n0   = blockIdx.x * 128;
    const int lane = t & 31;
    const int wid  = t >> 5;
    const int wm   = (wid >> 2) * 64;
    const int wn   = (wid & 3) * 32;
    const int gid  = lane >> 2;
    const int tg   = lane & 3;
    const int nk   = K / KC;
    const int rot  = (wid >> 2) << 1;

    const int a_thr = (((lane & 7) + ((lane >> 3) & 1) * 8) * PR + (lane >> 4) * 4) * 4;
    const int b_thr = (((lane & 7) + (lane >> 4) * 8) * PR + ((lane >> 3) & 1) * 4) * 4;

    float acc[4][4][4];
#pragma unroll
    for (int i = 0; i < 4; i++)
#pragma unroll
        for (int j = 0; j < 4; j++)
#pragma unroll
            for (int r = 0; r < 4; r++) acc[i][j][r] = 0.f;

#pragma unroll
    for (int s = 0; s < NSTAGE - 1; s++)
        pipe_issue(sb, s, A, BT, m0, n0, s * KC, K, t);

    int s = 0;
    for (int ki = 0; ki < nk; ki++) {
        CP_WAIT1();
        __syncthreads();

        const uint32_t As_addr = sb + (uint32_t)s * STG_B;
        const uint32_t Bs_addr = As_addr + T_BYTES;
        const bool do_pf = (ki + NSTAGE - 1 < nk);
        int sn = s + NSTAGE - 1;
        if (sn >= NSTAGE) sn -= NSTAGE;

#pragma unroll
        for (int gg = 0; gg < 4; gg++) {
            const int kk = ((gg + rot) & 3) * 8;
            unsigned a[4][4], bf[4][2];
#pragma unroll
            for (int mf = 0; mf < 4; mf++)
                LDSM4(a[mf][0], a[mf][1], a[mf][2], a[mf][3],
                      As_addr + (unsigned)(((wm + mf * 16) * PR + kk) * 4) + a_thr);
#pragma unroll
            for (int p = 0; p < 2; p++)
                LDSM4(bf[2 * p][0], bf[2 * p][1], bf[2 * p + 1][0], bf[2 * p + 1][1],
                      Bs_addr + (unsigned)(((wn + p * 16) * PR + kk) * 4) + b_thr);

            if (gg == 0) {
                if (do_pf)
                    pipe_issue(sb, sn, A, BT, m0, n0, (ki + NSTAGE - 1) * KC, K, t);
                else
                    CP_COMMIT();
            }

#pragma unroll
            for (int mf = 0; mf < 4; mf++)
#pragma unroll
                for (int nf = 0; nf < 4; nf++)
                    mma8(acc[mf][nf], a[mf][0], a[mf][1], a[mf][2], a[mf][3],
                         bf[nf][0], bf[nf][1]);
        }
        if (++s == NSTAGE) s = 0;
    }

#pragma unroll
    for (int mf = 0; mf < 4; mf++) {
#pragma unroll
        for (int nf = 0; nf < 4; nf++) {
            int row = m0 + wm + mf * 16 + gid;
            int col = n0 + wn + nf * 8 + tg * 2;
            float b0 = 0.f, b1 = 0.f;
            if (bias) { b0 = bias[col]; b1 = bias[col + 1]; }
            float o0 = acc[mf][nf][0] + b0, o1 = acc[mf][nf][1] + b1;
            float o2 = acc[mf][nf][2] + b0, o3 = acc[mf][nf][3] + b1;
            if (rnd_out) {
                o0 = rnd_tf32(o0); o1 = rnd_tf32(o1);
                o2 = rnd_tf32(o2); o3 = rnd_tf32(o3);
            }
            *(float2*)(C + (size_t)row * N + col) = make_float2(o0, o1);
            *(float2*)(C + (size_t)(row + 8) * N + col) = make_float2(o2, o3);
        }
    }
}

// ---------------- tf32 pre-round / transpose passes ----------------
__global__ void cvt_tf32_kernel(const float4* __restrict__ in, float4* __restrict__ out, int n4) {
    int i = blockIdx.x * blockDim.x + threadIdx.x;
    if (i < n4) {
        float4 v = in[i];
        v.x = rnd_tf32(v.x); v.y = rnd_tf32(v.y);
        v.z = rnd_tf32(v.z); v.w = rnd_tf32(v.w);
        out[i] = v;
    }
}

__global__ void transpose_tf32_kernel(const float* __restrict__ W, float* __restrict__ WT,
                                      int K, int N) {
    __shared__ float tbuf[32][33];
    int k0 = blockIdx.y * 32, n0 = blockIdx.x * 32;
    int x = threadIdx.x, y = threadIdx.y;
#pragma unroll
    for (int i = 0; i < 32; i += 8)
        tbuf[y + i][x] = W[(size_t)(k0 + y + i) * N + n0 + x];
    __syncthreads();
#pragma unroll
    for (int i = 0; i < 32; i += 8)
        WT[(size_t)(n0 + y + i) * K + k0 + x] = rnd_tf32(tbuf[x][y + i]);
}

// ============================================================
// Legacy single-buffer GEMM (small ragged K/V projections),
// epilogue now writes tf32-rounded output (consumed by attn).
// ============================================================
#define PA 136
#define PB 136

__device__ __forceinline__ void gemm_body(
    const float* __restrict__ A, const float* __restrict__ B,
    float* __restrict__ C, int M, int K, int N,
    unsigned* As, unsigned* Bs)
{
    const int t    = threadIdx.x;
    const int m0   = blockIdx.y * 128;
    const int n0   = blockIdx.x * 128;
    const int lane = t & 31;
    const int wid  = t >> 5;
    const int wm   = (wid >> 2) * 64;
    const int wn   = (wid & 3) * 32;
    const int gid  = lane >> 2;
    const int tg   = lane & 3;

    float acc[4][4][4];
#pragma unroll
    for (int i = 0; i < 4; i++)
#pragma unroll
        for (int j = 0; j < 4; j++)
#pragma unroll
            for (int r = 0; r < 4; r++) acc[i][j][r] = 0.f;

    for (int kt = 0; kt < K; kt += 16) {
#pragma unroll
        for (int i = 0; i < 2; i++) {
            int f  = t + i * 256;
            int m  = f >> 2;
            int kq = (f & 3) << 2;
            float4 val = make_float4(0.f, 0.f, 0.f, 0.f);
            if (m0 + m < M)
                val = *(const float4*)(A + (size_t)(m0 + m) * K + kt + kq);
            As[(kq + 0) * PA + m] = f2tf32(val.x);
            As[(kq + 1) * PA + m] = f2tf32(val.y);
            As[(kq + 2) * PA + m] = f2tf32(val.z);
            As[(kq + 3) * PA + m] = f2tf32(val.w);
        }
#pragma unroll
        for (int i = 0; i < 2; i++) {
            int f  = t + i * 256;
            int kr = f >> 5;
            int nq = (f & 31) << 2;
            float4 val = *(const float4*)(B + (size_t)(kt + kr) * N + n0 + nq);
            uint4 w;
            w.x = f2tf32(val.x); w.y = f2tf32(val.y);
            w.z = f2tf32(val.z); w.w = f2tf32(val.w);
            *(uint4*)(&Bs[kr * PB + nq]) = w;
        }
        __syncthreads();

#pragma unroll
        for (int kk = 0; kk < 16; kk += 8) {
            unsigned a[4][4], bf[4][2];
#pragma unroll
            for (int mf = 0; mf < 4; mf++) {
                int mb = wm + mf * 16 + gid;
                a[mf][0] = As[(kk + tg) * PA + mb];
                a[mf][1] = As[(kk + tg) * PA + mb + 8];
                a[mf][2] = As[(kk + tg + 4) * PA + mb];
                a[mf][3] = As[(kk + tg + 4) * PA + mb + 8];
            }
#pragma unroll
            for (int nf = 0; nf < 4; nf++) {
                int nb = wn + nf * 8 + gid;
                bf[nf][0] = Bs[(kk + tg) * PB + nb];
                bf[nf][1] = Bs[(kk + tg + 4) * PB + nb];
            }
#pragma unroll
            for (int mf = 0; mf < 4; mf++)
#pragma unroll
                for (int nf = 0; nf < 4; nf++)
                    mma8(acc[mf][nf], a[mf][0], a[mf][1], a[mf][2], a[mf][3],
                         bf[nf][0], bf[nf][1]);
        }
        __syncthreads();
    }

#pragma unroll
    for (int mf = 0; mf < 4; mf++) {
#pragma unroll
        for (int nf = 0; nf < 4; nf++) {
            int row = m0 + wm + mf * 16 + gid;
            int col = n0 + wn + nf * 8 + tg * 2;
            if (row < M)
                *(float2*)(C + (size_t)row * N + col) =
                    make_float2(rnd_tf32(acc[mf][nf][0]), rnd_tf32(acc[mf][nf][1]));
            if (row + 8 < M)
                *(float2*)(C + (size_t)(row + 8) * N + col) =
                    make_float2(rnd_tf32(acc[mf][nf][2]), rnd_tf32(acc[mf][nf][3]));
        }
    }
}

__global__ void __launch_bounds__(256, 2) gemm_tf32_dual(
    const float* __restrict__ A,
    const float* __restrict__ B0, float* __restrict__ C0,
    const float* __restrict__ B1, float* __restrict__ C1,
    int M, int K, int N)
{
    __shared__ unsigned As[16 * PA];
    __shared__ unsigned Bs[16 * PB];
    const float* B = blockIdx.z ? B1 : B0;
    float*       C = blockIdx.z ? C1 : C0;
    gemm_body(A, B, C, M, K, N, As, Bs);
}

// ============================================================
// Tensor-core attention v3: inputs pre-rounded tf32 in gmem,
// staging is pure cp.async (no cvt, latency hidden).
// smem words: Qs[128][68]=8704 | Kn[80][68]=5440 | Vs[80][72]=5760
// ============================================================
#define QS_OFF 0
#define KN_OFF 8704
#define VS_OFF 14144
#define ATTN_SMEM ((14144 + 80 * 72) * 4)   // 79616 bytes

__global__ void __launch_bounds__(256, 2) attn_mma(
    const float* __restrict__ q, const float* __restrict__ k,
    const float* __restrict__ v, float* __restrict__ o)
{
    extern __shared__ unsigned sm[];
    const uint32_t sb = smem_u32(sm);
    unsigned* Kn = sm + KN_OFF;
    unsigned* Vs = sm + VS_OFF;

    const int bh = blockIdx.y;
    const int b  = bh >> 4;
    const int h  = bh & 15;
    const int s0 = blockIdx.x * 128;
    const int t  = threadIdx.x;

    // zero-pad K/V rows 77..79 (st.shared, distinct addresses from cp.async)
    if (t < 192) {
        Kn[(77 + (t >> 6)) * 68 + (t & 63)] = 0;
        Vs[(77 + (t >> 6)) * 72 + (t & 63)] = 0;
    }

    // --- stage Q[128,64] via cp.async (pre-rounded tf32 bits) ---
    const float* qbase = q + (size_t)(b * SEQ + s0) * CDIM + h * DHEAD;
#pragma unroll
    for (int i = 0; i < 8; i++) {
        int f = t + i * 256;
        int r = f >> 4, c = f & 15;
        CP16(sb + (QS_OFF + r * 68 + c * 4) * 4, qbase + (size_t)r * CDIM + c * 4);
    }
    // --- stage K[77,64] ---
    const float* kbase = k + (size_t)(b * LTOK) * CDIM + h * DHEAD;
    for (int f = t; f < LTOK * 16; f += 256) {
        int r = f >> 4, c = f & 15;
        CP16(sb + (KN_OFF + r * 68 + c * 4) * 4, kbase + (size_t)r * CDIM + c * 4);
    }
    // --- stage V[77,64] ---
    const float* vbase = v + (size_t)(b * LTOK) * CDIM + h * DHEAD;
    for (int f = t; f < LTOK * 16; f += 256) {
        int r = f >> 4, c = f & 15;
        CP16(sb + (VS_OFF + r * 72 + c * 4) * 4, vbase + (size_t)r * CDIM + c * 4);
    }
    CP_COMMIT();
    CP_WAIT0();
    __syncthreads();

    const int wid = t >> 5, lane = t & 31;
    const int gid = lane >> 2, tg = lane & 3;
    const int wm  = wid * 16;
    const int r0  = wm + gid, r1 = wm + gid + 8;
    const unsigned* Qs = sm + QS_OFF;

    // --- S = Q K^T : 10 n-frags (80 cols, 77..79 dead), 8 k-frags ---
    float sacc[10][4];
#pragma unroll
    for (int nf = 0; nf < 10; nf++)
#pragma unroll
        for (int r = 0; r < 4; r++) sacc[nf][r] = 0.f;

#pragma unroll
    for (int kf = 0; kf < 8; kf++) {
        int kk = kf * 8;
        unsigned a0 = Qs[r0 * 68 + kk + tg];
        unsigned a1 = Qs[r1 * 68 + kk + tg];
        unsigned a2 = Qs[r0 * 68 + kk + tg + 4];
        unsigned a3 = Qs[r1 * 68 + kk + tg + 4];
#pragma unroll
        for (int nf = 0; nf < 10; nf++) {
            unsigned b0 = Kn[(nf * 8 + gid) * 68 + kk + tg];
            unsigned b1 = Kn[(nf * 8 + gid) * 68 + kk + tg + 4];
            mma8(sacc[nf], a0, a1, a2, a3, b0, b1);
        }
    }

    // --- masked softmax in registers ---
    const float scale = 0.125f;
    float sum0 = 0.f, sum1 = 0.f;
#pragma unroll
    for (int nf = 0; nf < 10; nf++) {
        int col = nf * 8 + tg * 2;
        float e00 = (col     < LTOK) ? rnd_tf32(__expf(sacc[nf][0] * scale)) : 0.f;
        float e01 = (col + 1 < LTOK) ? rnd_tf32(__expf(sacc[nf][1] * scale)) : 0.f;
        float e10 = (col     < LTOK) ? rnd_tf32(__expf(sacc[nf][2] * scale)) : 0.f;
        float e11 = (col + 1 < LTOK) ? rnd_tf32(__expf(sacc[nf][3] * scale)) : 0.f;
        sum0 += e00 + e01;
        sum1 += e10 + e11;
        sacc[nf][0] = e00; sacc[nf][1] = e01;
        sacc[nf][2] = e10; sacc[nf][3] = e11;
    }
    sum0 += __shfl_xor_sync(0xffffffffu, sum0, 1);
    sum0 += __shfl_xor_sync(0xffffffffu, sum0, 2);
    sum1 += __shfl_xor_sync(0xffffffffu, sum1, 1);
    sum1 += __shfl_xor_sync(0xffffffffu, sum1, 2);
    const float inv0 = 1.0f / sum0;
    const float inv1 = 1.0f / sum1;

    // --- O = P V : P in registers via intra-quad shfl ---
    float oacc[8][4];
#pragma unroll
    for (int nf = 0; nf < 8; nf++)
#pragma unroll
        for (int r = 0; r < 4; r++) oacc[nf][r] = 0.f;

    const int qbse = lane & 28;
    const int src1 = qbse | (tg >> 1);
    const int src2 = qbse | ((tg >> 1) + 2);
    const bool odd = tg & 1;

#pragma unroll
    for (int kf = 0; kf < 10; kf++) {
        float s00 = __shfl_sync(0xffffffffu, sacc[kf][0], src1);
        float s01 = __shfl_sync(0xffffffffu, sacc[kf][1], src1);
        float s10 = __shfl_sync(0xffffffffu, sacc[kf][2], src1);
        float s11 = __shfl_sync(0xffffffffu, sacc[kf][3], src1);
        float t00 = __shfl_sync(0xffffffffu, sacc[kf][0], src2);
        float t01 = __shfl_sync(0xffffffffu, sacc[kf][1], src2);
        float t10 = __shfl_sync(0xffffffffu, sacc[kf][2], src2);
        float t11 = __shfl_sync(0xffffffffu, sacc[kf][3], src2);
        unsigned a0 = __float_as_uint(odd ? s01 : s00);
        unsigned a1 = __float_as_uint(odd ? s11 : s10);
        unsigned a2 = __float_as_uint(odd ? t01 : t00);
        unsigned a3 = __float_as_uint(odd ? t11 : t10);
        int kk = kf * 8;
#pragma unroll
        for (int nf = 0; nf < 8; nf++) {
            unsigned b0 = Vs[(kk + tg) * 72 + nf * 8 + gid];
            unsigned b1 = Vs[(kk + tg + 4) * 72 + nf * 8 + gid];
            mma8(oacc[nf], a0, a1, a2, a3, b0, b1);
        }
    }

    // --- epilogue: normalize + tf32-round (Wo GEMM consumes this) ---
    float* ob0 = o + (size_t)(b * SEQ + s0 + r0) * CDIM + h * DHEAD;
    float* ob1 = o + (size_t)(b * SEQ + s0 + r1) * CDIM + h * DHEAD;
#pragma unroll
    for (int nf = 0; nf < 8; nf++) {
        int col = nf * 8 + tg * 2;
        *(float2*)(ob0 + col) = make_float2(rnd_tf32(oacc[nf][0] * inv0),
                                            rnd_tf32(oacc[nf][1] * inv0));
        *(float2*)(ob1 + col) = make_float2(rnd_tf32(oacc[nf][2] * inv1),
                                            rnd_tf32(oacc[nf][3] * inv1));
    }
}

// ============================================================
// launch
// ============================================================
extern "C" void kernel_launch(void* const* d_in, const int* in_sizes, int n_in,
                              void* d_out, int out_size)
{
    const float* hs  = (const float*)d_in[0];
    const float* enc = (const float*)d_in[1];
    const float* Wq  = (const float*)d_in[2];
    const float* Wk  = (const float*)d_in[3];
    const float* Wv  = (const float*)d_in[4];
    const float* Wo  = (const float*)d_in[5];
    const float* bo  = (const float*)d_in[6];
    float* out = (float*)d_out;
    (void)in_sizes; (void)n_in; (void)out_size;

    float *qb, *kb, *vb, *ab, *hsb, *wqt, *wot;
    cudaGetSymbolAddress((void**)&qb,  g_q);
    cudaGetSymbolAddress((void**)&kb,  g_k);
    cudaGetSymbolAddress((void**)&vb,  g_v);
    cudaGetSymbolAddress((void**)&ab,  g_attn);
    cudaGetSymbolAddress((void**)&hsb, g_hs);
    cudaGetSymbolAddress((void**)&wqt, g_wqt);
    cudaGetSymbolAddress((void**)&wot, g_wot);

    // pre-round A operand; round+transpose weights for B operand
    cvt_tf32_kernel<<<(MQ * CDIM / 4 + 255) / 256, 256>>>((const float4*)hs, (float4*)hsb, MQ * CDIM / 4);
    transpose_tf32_kernel<<<dim3(CDIM / 32, CDIM / 32), dim3(32, 8)>>>(Wq, wqt, CDIM, CDIM);
    transpose_tf32_kernel<<<dim3(CDIM / 32, CDIM / 32), dim3(32, 8)>>>(Wo, wot, CDIM, CDIM);

    cudaFuncSetAttribute(gemm_pipe, cudaFuncAttributeMaxDynamicSharedMemorySize, PIPE_SMEM);

    // q = hs @ Wq  (rounded output -> attn consumes raw bits)
    gemm_pipe<<<dim3(CDIM / 128, MQ / 128), 256, PIPE_SMEM>>>(hsb, wqt, qb, MQ, CDIM, CDIM, nullptr, 1);

    // k,v = enc @ {Wk,Wv}  (rounded outputs)
    gemm_tf32_dual<<<dim3(CDIM / 128, (MKV + 127) / 128, 2), 256>>>(
        enc, Wk, kb, Wv, vb, MKV, CENC, CDIM);

    // tensor-core attention (cp.async staging)
    cudaFuncSetAttribute(attn_mma, cudaFuncAttributeMaxDynamicSharedMemorySize, ATTN_SMEM);
    attn_mma<<<dim3(SEQ / 128, BATCH * NHEAD), 256, ATTN_SMEM>>>(qb, kb, vb, ab);

    // out = attn @ Wo + bo  (raw fp32 output)
    gemm_pipe<<<dim3(CDIM / 128, MQ / 128), 256, PIPE_SMEM>>>(ab, wot, out, MQ, CDIM, CDIM, bo, 0);
}

// round 14
// speedup vs baseline: 1.2495x; 1.0687x over previous
#include <cuda_runtime.h>
#include <cstdint>

// ---------------- problem constants ----------------
#define BATCH   16
#define SEQ     4096
#define CDIM    1024
#define NHEAD   16
#define DHEAD   64
#define LTOK    77
#define CENC    768
#define MQ      (BATCH*SEQ)      // 65536
#define MKV     (BATCH*LTOK)     // 1232

// ---------------- scratch ----------------
__device__ float g_q[(size_t)MQ * CDIM];
__device__ float g_attn[(size_t)MQ * CDIM];
__device__ float g_k[(size_t)MKV * CDIM];
__device__ float g_v[(size_t)MKV * CDIM];
__device__ float g_wqt[CDIM * CDIM];
__device__ float g_wot[CDIM * CDIM];

__device__ __forceinline__ unsigned f2tf32(float x) {
    unsigned r;
    asm("cvt.rna.tf32.f32 %0, %1;" : "=r"(r) : "f"(x));
    return r;
}
__device__ __forceinline__ float rnd_tf32(float x) { return __uint_as_float(f2tf32(x)); }

__device__ __forceinline__ uint32_t smem_u32(const void* p) {
    uint32_t a;
    asm("{ .reg .u64 t; cvta.to.shared.u64 t, %1; cvt.u32.u64 %0, t; }" : "=r"(a) : "l"(p));
    return a;
}
#define CP16(dst, src) \
    asm volatile("cp.async.cg.shared.global [%0], [%1], 16;" :: "r"(dst), "l"(src) : "memory")
#define CP_COMMIT() asm volatile("cp.async.commit_group;" ::: "memory")
#define CP_WAIT1()  asm volatile("cp.async.wait_group 1;" ::: "memory")
#define CP_WAIT0()  asm volatile("cp.async.wait_group 0;" ::: "memory")

#define LDSM4(r0, r1, r2, r3, addr) \
    asm volatile("ldmatrix.sync.aligned.m8n8.x4.shared.b16 {%0,%1,%2,%3}, [%4];" \
        : "=r"(r0), "=r"(r1), "=r"(r2), "=r"(r3) : "r"(addr))

__device__ __forceinline__ void mma8(float* d, unsigned a0, unsigned a1,
                                     unsigned a2, unsigned a3,
                                     unsigned b0, unsigned b1) {
    asm volatile(
        "mma.sync.aligned.m16n8k8.row.col.f32.tf32.tf32.f32 "
        "{%0,%1,%2,%3}, {%4,%5,%6,%7}, {%8,%9}, {%0,%1,%2,%3};"
        : "+f"(d[0]), "+f"(d[1]), "+f"(d[2]), "+f"(d[3])
        : "r"(a0), "r"(a1), "r"(a2), "r"(a3), "r"(b0), "r"(b1));
}

// ============================================================
// Pipelined TF32 GEMM (R12 config; RND is a template constant).
// C[M,N] = A[M,K] @ BT[N,K]^T (+bias). BT pre-rounded tf32;
// A may be raw fp32 (mma truncates the low mantissa bits).
// ============================================================
#define NSTAGE  3
#define KC      32
#define PR      36
#define T_BYTES (128 * PR * 4)
#define STG_B   (2 * T_BYTES)
#define PIPE_SMEM (NSTAGE * STG_B)

__device__ __forceinline__ void pipe_issue(
    uint32_t sb, int s, const float* __restrict__ A, const float* __restrict__ BT,
    int m0, int n0, int kt, int K, int t)
{
    uint32_t base = sb + s * STG_B;
#pragma unroll
    for (int i = 0; i < 4; i++) {
        int f = t + i * 256;
        int r = f >> 3, c = f & 7;
        CP16(base + r * (PR * 4) + c * 16,
             A + (size_t)(m0 + r) * K + kt + c * 4);
    }
#pragma unroll
    for (int i = 0; i < 4; i++) {
        int f = t + i * 256;
        int r = f >> 3, c = f & 7;
        CP16(base + T_BYTES + r * (PR * 4) + c * 16,
             BT + (size_t)(n0 + r) * K + kt + c * 4);
    }
    CP_COMMIT();
}

template <int RND>
__global__ void __launch_bounds__(256, 2) gemm_pipe(
    const float* __restrict__ A, const float* __restrict__ BT,
    float* __restrict__ C, int M, int K, int N,
    const float* __restrict__ bias)
{
    extern __shared__ char smem[];
    const uint32_t sb = smem_u32(smem);

    const int t    = threadIdx.x;
    const int m0   = blockIdx.y * 128;
    const int n0   = blockIdx.x * 128;
    const int lane = t & 31;
    const int wid  = t >> 5;
    const int wm   = (wid >> 2) * 64;
    const int wn   = (wid & 3) * 32;
    const int gid  = lane >> 2;
    const int tg   = lane & 3;
    const int nk   = K / KC;
    const int rot  = (wid >> 2) << 1;

    const int a_thr = (((lane & 7) + ((lane >> 3) & 1) * 8) * PR + (lane >> 4) * 4) * 4;
    const int b_thr = (((lane & 7) + (lane >> 4) * 8) * PR + ((lane >> 3) & 1) * 4) * 4;

    float acc[4][4][4];
#pragma unroll
    for (int i = 0; i < 4; i++)
#pragma unroll
        for (int j = 0; j < 4; j++)
#pragma unroll
            for (int r = 0; r < 4; r++) acc[i][j][r] = 0.f;

#pragma unroll
    for (int s = 0; s < NSTAGE - 1; s++)
        pipe_issue(sb, s, A, BT, m0, n0, s * KC, K, t);

    int s = 0;
    for (int ki = 0; ki < nk; ki++) {
        CP_WAIT1();
        __syncthreads();

        const uint32_t As_addr = sb + (uint32_t)s * STG_B;
        const uint32_t Bs_addr = As_addr + T_BYTES;
        const bool do_pf = (ki + NSTAGE - 1 < nk);
        int sn = s + NSTAGE - 1;
        if (sn >= NSTAGE) sn -= NSTAGE;

#pragma unroll
        for (int gg = 0; gg < 4; gg++) {
            const int kk = ((gg + rot) & 3) * 8;
            unsigned a[4][4], bf[4][2];
#pragma unroll
            for (int mf = 0; mf < 4; mf++)
                LDSM4(a[mf][0], a[mf][1], a[mf][2], a[mf][3],
                      As_addr + (unsigned)(((wm + mf * 16) * PR + kk) * 4) + a_thr);
#pragma unroll
            for (int p = 0; p < 2; p++)
                LDSM4(bf[2 * p][0], bf[2 * p][1], bf[2 * p + 1][0], bf[2 * p + 1][1],
                      Bs_addr + (unsigned)(((wn + p * 16) * PR + kk) * 4) + b_thr);

            if (gg == 0) {
                if (do_pf)
                    pipe_issue(sb, sn, A, BT, m0, n0, (ki + NSTAGE - 1) * KC, K, t);
                else
                    CP_COMMIT();
            }

#pragma unroll
            for (int mf = 0; mf < 4; mf++)
#pragma unroll
                for (int nf = 0; nf < 4; nf++)
                    mma8(acc[mf][nf], a[mf][0], a[mf][1], a[mf][2], a[mf][3],
                         bf[nf][0], bf[nf][1]);
        }
        if (++s == NSTAGE) s = 0;
    }

#pragma unroll
    for (int mf = 0; mf < 4; mf++) {
#pragma unroll
        for (int nf = 0; nf < 4; nf++) {
            int row = m0 + wm + mf * 16 + gid;
            int col = n0 + wn + nf * 8 + tg * 2;
            float b0 = 0.f, b1 = 0.f;
            if (bias) { b0 = bias[col]; b1 = bias[col + 1]; }
            float o0 = acc[mf][nf][0] + b0, o1 = acc[mf][nf][1] + b1;
            float o2 = acc[mf][nf][2] + b0, o3 = acc[mf][nf][3] + b1;
            if (RND) {
                o0 = rnd_tf32(o0); o1 = rnd_tf32(o1);
                o2 = rnd_tf32(o2); o3 = rnd_tf32(o3);
            }
            *(float2*)(C + (size_t)row * N + col) = make_float2(o0, o1);
            *(float2*)(C + (size_t)(row + 8) * N + col) = make_float2(o2, o3);
        }
    }
}

// ---------------- weight round+transpose pass ----------------
__global__ void transpose_tf32_kernel(const float* __restrict__ W, float* __restrict__ WT,
                                      int K, int N) {
    __shared__ float tbuf[32][33];
    int k0 = blockIdx.y * 32, n0 = blockIdx.x * 32;
    int x = threadIdx.x, y = threadIdx.y;
#pragma unroll
    for (int i = 0; i < 32; i += 8)
        tbuf[y + i][x] = W[(size_t)(k0 + y + i) * N + n0 + x];
    __syncthreads();
#pragma unroll
    for (int i = 0; i < 32; i += 8)
        WT[(size_t)(n0 + y + i) * K + k0 + x] = rnd_tf32(tbuf[x][y + i]);
}

// ============================================================
// Legacy single-buffer GEMM (small ragged K/V projections),
// epilogue writes tf32-rounded output (consumed raw by attn).
// ============================================================
#define PA 136
#define PB 136

__device__ __forceinline__ void gemm_body(
    const float* __restrict__ A, const float* __restrict__ B,
    float* __restrict__ C, int M, int K, int N,
    unsigned* As, unsigned* Bs)
{
    const int t    = threadIdx.x;
    const int m0   = blockIdx.y * 128;
    const int n0   = blockIdx.x * 128;
    const int lane = t & 31;
    const int wid  = t >> 5;
    const int wm   = (wid >> 2) * 64;
    const int wn   = (wid & 3) * 32;
    const int gid  = lane >> 2;
    const int tg   = lane & 3;

    float acc[4][4][4];
#pragma unroll
    for (int i = 0; i < 4; i++)
#pragma unroll
        for (int j = 0; j < 4; j++)
#pragma unroll
            for (int r = 0; r < 4; r++) acc[i][j][r] = 0.f;

    for (int kt = 0; kt < K; kt += 16) {
#pragma unroll
        for (int i = 0; i < 2; i++) {
            int f  = t + i * 256;
            int m  = f >> 2;
            int kq = (f & 3) << 2;
            float4 val = make_float4(0.f, 0.f, 0.f, 0.f);
            if (m0 + m < M)
                val = *(const float4*)(A + (size_t)(m0 + m) * K + kt + kq);
            As[(kq + 0) * PA + m] = f2tf32(val.x);
            As[(kq + 1) * PA + m] = f2tf32(val.y);
            As[(kq + 2) * PA + m] = f2tf32(val.z);
            As[(kq + 3) * PA + m] = f2tf32(val.w);
        }
#pragma unroll
        for (int i = 0; i < 2; i++) {
            int f  = t + i * 256;
            int kr = f >> 5;
            int nq = (f & 31) << 2;
            float4 val = *(const float4*)(B + (size_t)(kt + kr) * N + n0 + nq);
            uint4 w;
            w.x = f2tf32(val.x); w.y = f2tf32(val.y);
            w.z = f2tf32(val.z); w.w = f2tf32(val.w);
            *(uint4*)(&Bs[kr * PB + nq]) = w;
        }
        __syncthreads();

#pragma unroll
        for (int kk = 0; kk < 16; kk += 8) {
            unsigned a[4][4], bf[4][2];
#pragma unroll
            for (int mf = 0; mf < 4; mf++) {
                int mb = wm + mf * 16 + gid;
                a[mf][0] = As[(kk + tg) * PA + mb];
                a[mf][1] = As[(kk + tg) * PA + mb + 8];
                a[mf][2] = As[(kk + tg + 4) * PA + mb];
                a[mf][3] = As[(kk + tg + 4) * PA + mb + 8];
            }
#pragma unroll
            for (int nf = 0; nf < 4; nf++) {
                int nb = wn + nf * 8 + gid;
                bf[nf][0] = Bs[(kk + tg) * PB + nb];
                bf[nf][1] = Bs[(kk + tg + 4) * PB + nb];
            }
#pragma unroll
            for (int mf = 0; mf < 4; mf++)
#pragma unroll
                for (int nf = 0; nf < 4; nf++)
                    mma8(acc[mf][nf], a[mf][0], a[mf][1], a[mf][2], a[mf][3],
                         bf[nf][0], bf[nf][1]);
        }
        __syncthreads();
    }

#pragma unroll
    for (int mf = 0; mf < 4; mf++) {
#pragma unroll
        for (int nf = 0; nf < 4; nf++) {
            int row = m0 + wm + mf * 16 + gid;
            int col = n0 + wn + nf * 8 + tg * 2;
            if (row < M)
                *(float2*)(C + (size_t)row * N + col) =
                    make_float2(rnd_tf32(acc[mf][nf][0]), rnd_tf32(acc[mf][nf][1]));
            if (row + 8 < M)
                *(float2*)(C + (size_t)(row + 8) * N + col) =
                    make_float2(rnd_tf32(acc[mf][nf][2]), rnd_tf32(acc[mf][nf][3]));
        }
    }
}

__global__ void __launch_bounds__(256, 2) gemm_tf32_dual(
    const float* __restrict__ A,
    const float* __restrict__ B0, float* __restrict__ C0,
    const float* __restrict__ B1, float* __restrict__ C1,
    int M, int K, int N)
{
    __shared__ unsigned As[16 * PA];
    __shared__ unsigned Bs[16 * PB];
    const float* B = blockIdx.z ? B1 : B0;
    float*       C = blockIdx.z ? C1 : C0;
    gemm_body(A, B, C, M, K, N, As, Bs);
}

// ============================================================
// Tensor-core attention (R13: cp.async staging, pre-rounded inputs)
// ============================================================
#define QS_OFF 0
#define KN_OFF 8704
#define VS_OFF 14144
#define ATTN_SMEM ((14144 + 80 * 72) * 4)   // 79616 bytes

__global__ void __launch_bounds__(256, 2) attn_mma(
    const float* __restrict__ q, const float* __restrict__ k,
    const float* __restrict__ v, float* __restrict__ o)
{
    extern __shared__ unsigned sm[];
    const uint32_t sb = smem_u32(sm);
    unsigned* Kn = sm + KN_OFF;
    unsigned* Vs = sm + VS_OFF;

    const int bh = blockIdx.y;
    const int b  = bh >> 4;
    const int h  = bh & 15;
    const int s0 = blockIdx.x * 128;
    const int t  = threadIdx.x;

    if (t < 192) {
        Kn[(77 + (t >> 6)) * 68 + (t & 63)] = 0;
        Vs[(77 + (t >> 6)) * 72 + (t & 63)] = 0;
    }

    const float* qbase = q + (size_t)(b * SEQ + s0) * CDIM + h * DHEAD;
#pragma unroll
    for (int i = 0; i < 8; i++) {
        int f = t + i * 256;
        int r = f >> 4, c = f & 15;
        CP16(sb + (QS_OFF + r * 68 + c * 4) * 4, qbase + (size_t)r * CDIM + c * 4);
    }
    const float* kbase = k + (size_t)(b * LTOK) * CDIM + h * DHEAD;
    for (int f = t; f < LTOK * 16; f += 256) {
        int r = f >> 4, c = f & 15;
        CP16(sb + (KN_OFF + r * 68 + c * 4) * 4, kbase + (size_t)r * CDIM + c * 4);
    }
    const float* vbase = v + (size_t)(b * LTOK) * CDIM + h * DHEAD;
    for (int f = t; f < LTOK * 16; f += 256) {
        int r = f >> 4, c = f & 15;
        CP16(sb + (VS_OFF + r * 72 + c * 4) * 4, vbase + (size_t)r * CDIM + c * 4);
    }
    CP_COMMIT();
    CP_WAIT0();
    __syncthreads();

    const int wid = t >> 5, lane = t & 31;
    const int gid = lane >> 2, tg = lane & 3;
    const int wm  = wid * 16;
    const int r0  = wm + gid, r1 = wm + gid + 8;
    const unsigned* Qs = sm + QS_OFF;

    float sacc[10][4];
#pragma unroll
    for (int nf = 0; nf < 10; nf++)
#pragma unroll
        for (int r = 0; r < 4; r++) sacc[nf][r] = 0.f;

#pragma unroll
    for (int kf = 0; kf < 8; kf++) {
        int kk = kf * 8;
        unsigned a0 = Qs[r0 * 68 + kk + tg];
        unsigned a1 = Qs[r1 * 68 + kk + tg];
        unsigned a2 = Qs[r0 * 68 + kk + tg + 4];
        unsigned a3 = Qs[r1 * 68 + kk + tg + 4];
#pragma unroll
        for (int nf = 0; nf < 10; nf++) {
            unsigned b0 = Kn[(nf * 8 + gid) * 68 + kk + tg];
            unsigned b1 = Kn[(nf * 8 + gid) * 68 + kk + tg + 4];
            mma8(sacc[nf], a0, a1, a2, a3, b0, b1);
        }
    }

    const float scale = 0.125f;
    float sum0 = 0.f, sum1 = 0.f;
#pragma unroll
    for (int nf = 0; nf < 10; nf++) {
        int col = nf * 8 + tg * 2;
        float e00 = (col     < LTOK) ? rnd_tf32(__expf(sacc[nf][0] * scale)) : 0.f;
        float e01 = (col + 1 < LTOK) ? rnd_tf32(__expf(sacc[nf][1] * scale)) : 0.f;
        float e10 = (col     < LTOK) ? rnd_tf32(__expf(sacc[nf][2] * scale)) : 0.f;
        float e11 = (col + 1 < LTOK) ? rnd_tf32(__expf(sacc[nf][3] * scale)) : 0.f;
        sum0 += e00 + e01;
        sum1 += e10 + e11;
        sacc[nf][0] = e00; sacc[nf][1] = e01;
        sacc[nf][2] = e10; sacc[nf][3] = e11;
    }
    sum0 += __shfl_xor_sync(0xffffffffu, sum0, 1);
    sum0 += __shfl_xor_sync(0xffffffffu, sum0, 2);
    sum1 += __shfl_xor_sync(0xffffffffu, sum1, 1);
    sum1 += __shfl_xor_sync(0xffffffffu, sum1, 2);
    const float inv0 = 1.0f / sum0;
    const float inv1 = 1.0f / sum1;

    float oacc[8][4];
#pragma unroll
    for (int nf = 0; nf < 8; nf++)
#pragma unroll
        for (int r = 0; r < 4; r++) oacc[nf][r] = 0.f;

    const int qbse = lane & 28;
    const int src1 = qbse | (tg >> 1);
    const int src2 = qbse | ((tg >> 1) + 2);
    const bool odd = tg & 1;

#pragma unroll
    for (int kf = 0; kf < 10; kf++) {
        float s00 = __shfl_sync(0xffffffffu, sacc[kf][0], src1);
        float s01 = __shfl_sync(0xffffffffu, sacc[kf][1], src1);
        float s10 = __shfl_sync(0xffffffffu, sacc[kf][2], src1);
        float s11 = __shfl_sync(0xffffffffu, sacc[kf][3], src1);
        float t00 = __shfl_sync(0xffffffffu, sacc[kf][0], src2);
        float t01 = __shfl_sync(0xffffffffu, sacc[kf][1], src2);
        float t10 = __shfl_sync(0xffffffffu, sacc[kf][2], src2);
        float t11 = __shfl_sync(0xffffffffu, sacc[kf][3], src2);
        unsigned a0 = __float_as_uint(odd ? s01 : s00);
        unsigned a1 = __float_as_uint(odd ? s11 : s10);
        unsigned a2 = __float_as_uint(odd ? t01 : t00);
        unsigned a3 = __float_as_uint(odd ? t11 : t10);
        int kk = kf * 8;
#pragma unroll
        for (int nf = 0; nf < 8; nf++) {
            unsigned b0 = Vs[(kk + tg) * 72 + nf * 8 + gid];
            unsigned b1 = Vs[(kk + tg + 4) * 72 + nf * 8 + gid];
            mma8(oacc[nf], a0, a1, a2, a3, b0, b1);
        }
    }

    float* ob0 = o + (size_t)(b * SEQ + s0 + r0) * CDIM + h * DHEAD;
    float* ob1 = o + (size_t)(b * SEQ + s0 + r1) * CDIM + h * DHEAD;
#pragma unroll
    for (int nf = 0; nf < 8; nf++) {
        int col = nf * 8 + tg * 2;
        *(float2*)(ob0 + col) = make_float2(rnd_tf32(oacc[nf][0] * inv0),
                                            rnd_tf32(oacc[nf][1] * inv0));
        *(float2*)(ob1 + col) = make_float2(rnd_tf32(oacc[nf][2] * inv1),
                                            rnd_tf32(oacc[nf][3] * inv1));
    }
}

// ============================================================
// launch
// ============================================================
extern "C" void kernel_launch(void* const* d_in, const int* in_sizes, int n_in,
                              void* d_out, int out_size)
{
    const float* hs  = (const float*)d_in[0];
    const float* enc = (const float*)d_in[1];
    const float* Wq  = (const float*)d_in[2];
    const float* Wk  = (const float*)d_in[3];
    const float* Wv  = (const float*)d_in[4];
    const float* Wo  = (const float*)d_in[5];
    const float* bo  = (const float*)d_in[6];
    float* out = (float*)d_out;
    (void)in_sizes; (void)n_in; (void)out_size;

    float *qb, *kb, *vb, *ab, *wqt, *wot;
    cudaGetSymbolAddress((void**)&qb,  g_q);
    cudaGetSymbolAddress((void**)&kb,  g_k);
    cudaGetSymbolAddress((void**)&vb,  g_v);
    cudaGetSymbolAddress((void**)&ab,  g_attn);
    cudaGetSymbolAddress((void**)&wqt, g_wqt);
    cudaGetSymbolAddress((void**)&wot, g_wot);

    // round+transpose weights for the B operand (hs fed raw; mma truncates)
    transpose_tf32_kernel<<<dim3(CDIM / 32, CDIM / 32), dim3(32, 8)>>>(Wq, wqt, CDIM, CDIM);
    transpose_tf32_kernel<<<dim3(CDIM / 32, CDIM / 32), dim3(32, 8)>>>(Wo, wot, CDIM, CDIM);

    cudaFuncSetAttribute(gemm_pipe<0>, cudaFuncAttributeMaxDynamicSharedMemorySize, PIPE_SMEM);
    cudaFuncSetAttribute(gemm_pipe<1>, cudaFuncAttributeMaxDynamicSharedMemorySize, PIPE_SMEM);

    // q = hs @ Wq  (rounded output -> attn consumes raw bits)
    gemm_pipe<1><<<dim3(CDIM / 128, MQ / 128), 256, PIPE_SMEM>>>(hs, wqt, qb, MQ, CDIM, CDIM, nullptr);

    // k,v = enc @ {Wk,Wv}  (rounded outputs)
    gemm_tf32_dual<<<dim3(CDIM / 128, (MKV + 127) / 128, 2), 256>>>(
        enc, Wk, kb, Wv, vb, MKV, CENC, CDIM);

    // tensor-core attention (cp.async staging)
    cudaFuncSetAttribute(attn_mma, cudaFuncAttributeMaxDynamicSharedMemorySize, ATTN_SMEM);
    attn_mma<<<dim3(SEQ / 128, BATCH * NHEAD), 256, ATTN_SMEM>>>(qb, kb, vb, ab);

    // out = attn @ Wo + bo  (raw fp32 output)
    gemm_pipe<0><<<dim3(CDIM / 128, MQ / 128), 256, PIPE_SMEM>>>(ab, wot, out, MQ, CDIM, CDIM, bo);
}

// round 15
// speedup vs baseline: 1.2552x; 1.0046x over previous
#include <cuda_runtime.h>
#include <cstdint>

// ---------------- problem constants ----------------
#define BATCH   16
#define SEQ     4096
#define CDIM    1024
#define NHEAD   16
#define DHEAD   64
#define LTOK    77
#define CENC    768
#define MQ      (BATCH*SEQ)      // 65536
#define MKV     (BATCH*LTOK)     // 1232

// ---------------- scratch ----------------
__device__ float g_q[(size_t)MQ * CDIM];
__device__ float g_attn[(size_t)MQ * CDIM];
__device__ float g_k[(size_t)MKV * CDIM];
__device__ float g_v[(size_t)MKV * CDIM];
__device__ float g_wqt[CDIM * CDIM];
__device__ float g_wot[CDIM * CDIM];
__device__ float g_wkt[CDIM * CENC];
__device__ float g_wvt[CDIM * CENC];

__device__ __forceinline__ unsigned f2tf32(float x) {
    unsigned r;
    asm("cvt.rna.tf32.f32 %0, %1;" : "=r"(r) : "f"(x));
    return r;
}
__device__ __forceinline__ float rnd_tf32(float x) { return __uint_as_float(f2tf32(x)); }

__device__ __forceinline__ uint32_t smem_u32(const void* p) {
    uint32_t a;
    asm("{ .reg .u64 t; cvta.to.shared.u64 t, %1; cvt.u32.u64 %0, t; }" : "=r"(a) : "l"(p));
    return a;
}
#define CP16(dst, src) \
    asm volatile("cp.async.cg.shared.global [%0], [%1], 16;" :: "r"(dst), "l"(src) : "memory")
#define CP_COMMIT() asm volatile("cp.async.commit_group;" ::: "memory")
#define CP_WAIT1()  asm volatile("cp.async.wait_group 1;" ::: "memory")
#define CP_WAIT0()  asm volatile("cp.async.wait_group 0;" ::: "memory")

#define LDSM4(r0, r1, r2, r3, addr) \
    asm volatile("ldmatrix.sync.aligned.m8n8.x4.shared.b16 {%0,%1,%2,%3}, [%4];" \
        : "=r"(r0), "=r"(r1), "=r"(r2), "=r"(r3) : "r"(addr))

__device__ __forceinline__ void mma8(float* d, unsigned a0, unsigned a1,
                                     unsigned a2, unsigned a3,
                                     unsigned b0, unsigned b1) {
    asm volatile(
        "mma.sync.aligned.m16n8k8.row.col.f32.tf32.tf32.f32 "
        "{%0,%1,%2,%3}, {%4,%5,%6,%7}, {%8,%9}, {%0,%1,%2,%3};"
        : "+f"(d[0]), "+f"(d[1]), "+f"(d[2]), "+f"(d[3])
        : "r"(a0), "r"(a1), "r"(a2), "r"(a3), "r"(b0), "r"(b1));
}

// ============================================================
// Pipelined TF32 GEMM body (R12 config). RND/CLAMP templated.
// C[M,N] = A[M,K] @ BT[N,K]^T (+bias). BT pre-rounded tf32;
// A may be raw fp32 (mma truncates). CLAMP: ragged-M A loads.
// ============================================================
#define NSTAGE  3
#define KC      32
#define PR      36
#define T_BYTES (128 * PR * 4)
#define STG_B   (2 * T_BYTES)
#define PIPE_SMEM (NSTAGE * STG_B)

template <bool CLAMP>
__device__ __forceinline__ void pipe_issue(
    uint32_t sb, int s, const float* __restrict__ A, const float* __restrict__ BT,
    int m0, int n0, int kt, int M, int K, int t)
{
    uint32_t base = sb + s * STG_B;
#pragma unroll
    for (int i = 0; i < 4; i++) {
        int f = t + i * 256;
        int r = f >> 3, c = f & 7;
        int row = m0 + r;
        if (CLAMP) row = (row < M) ? row : (M - 1);
        CP16(base + r * (PR * 4) + c * 16,
             A + (size_t)row * K + kt + c * 4);
    }
#pragma unroll
    for (int i = 0; i < 4; i++) {
        int f = t + i * 256;
        int r = f >> 3, c = f & 7;
        CP16(base + T_BYTES + r * (PR * 4) + c * 16,
             BT + (size_t)(n0 + r) * K + kt + c * 4);
    }
    CP_COMMIT();
}

template <int RND, bool CLAMP>
__device__ __forceinline__ void pipe_body(
    char* smem, const float* __restrict__ A, const float* __restrict__ BT,
    float* __restrict__ C, int M, int K, int N, const float* __restrict__ bias)
{
    const uint32_t sb = smem_u32(smem);
    const int t    = threadIdx.x;
    const int m0   = blockIdx.y * 128;
    const int n0   = blockIdx.x * 128;
    const int lane = t & 31;
    const int wid  = t >> 5;
    const int wm   = (wid >> 2) * 64;
    const int wn   = (wid & 3) * 32;
    const int gid  = lane >> 2;
    const int tg   = lane & 3;
    const int nk   = K / KC;
    const int rot  = (wid >> 2) << 1;

    const int a_thr = (((lane & 7) + ((lane >> 3) & 1) * 8) * PR + (lane >> 4) * 4) * 4;
    const int b_thr = (((lane & 7) + (lane >> 4) * 8) * PR + ((lane >> 3) & 1) * 4) * 4;

    float acc[4][4][4];
#pragma unroll
    for (int i = 0; i < 4; i++)
#pragma unroll
        for (int j = 0; j < 4; j++)
#pragma unroll
            for (int r = 0; r < 4; r++) acc[i][j][r] = 0.f;

#pragma unroll
    for (int s = 0; s < NSTAGE - 1; s++)
        pipe_issue<CLAMP>(sb, s, A, BT, m0, n0, s * KC, M, K, t);

    int s = 0;
    for (int ki = 0; ki < nk; ki++) {
        CP_WAIT1();
        __syncthreads();

        const uint32_t As_addr = sb + (uint32_t)s * STG_B;
        const uint32_t Bs_addr = As_addr + T_BYTES;
        const bool do_pf = (ki + NSTAGE - 1 < nk);
        int sn = s + NSTAGE - 1;
        if (sn >= NSTAGE) sn -= NSTAGE;

#pragma unroll
        for (int gg = 0; gg < 4; gg++) {
            const int kk = ((gg + rot) & 3) * 8;
            unsigned a[4][4], bf[4][2];
#pragma unroll
            for (int mf = 0; mf < 4; mf++)
                LDSM4(a[mf][0], a[mf][1], a[mf][2], a[mf][3],
                      As_addr + (unsigned)(((wm + mf * 16) * PR + kk) * 4) + a_thr);
#pragma unroll
            for (int p = 0; p < 2; p++)
                LDSM4(bf[2 * p][0], bf[2 * p][1], bf[2 * p + 1][0], bf[2 * p + 1][1],
                      Bs_addr + (unsigned)(((wn + p * 16) * PR + kk) * 4) + b_thr);

            if (gg == 0) {
                if (do_pf)
                    pipe_issue<CLAMP>(sb, sn, A, BT, m0, n0, (ki + NSTAGE - 1) * KC, M, K, t);
                else
                    CP_COMMIT();
            }

#pragma unroll
            for (int mf = 0; mf < 4; mf++)
#pragma unroll
                for (int nf = 0; nf < 4; nf++)
                    mma8(acc[mf][nf], a[mf][0], a[mf][1], a[mf][2], a[mf][3],
                         bf[nf][0], bf[nf][1]);
        }
        if (++s == NSTAGE) s = 0;
    }

#pragma unroll
    for (int mf = 0; mf < 4; mf++) {
#pragma unroll
        for (int nf = 0; nf < 4; nf++) {
            int row = m0 + wm + mf * 16 + gid;
            int col = n0 + wn + nf * 8 + tg * 2;
            float b0 = 0.f, b1 = 0.f;
            if (bias) { b0 = bias[col]; b1 = bias[col + 1]; }
            float o0 = acc[mf][nf][0] + b0, o1 = acc[mf][nf][1] + b1;
            float o2 = acc[mf][nf][2] + b0, o3 = acc[mf][nf][3] + b1;
            if (RND) {
                o0 = rnd_tf32(o0); o1 = rnd_tf32(o1);
                o2 = rnd_tf32(o2); o3 = rnd_tf32(o3);
            }
            if (!CLAMP || row < M)
                *(float2*)(C + (size_t)row * N + col) = make_float2(o0, o1);
            if (!CLAMP || row + 8 < M)
                *(float2*)(C + (size_t)(row + 8) * N + col) = make_float2(o2, o3);
        }
    }
}

template <int RND>
__global__ void __launch_bounds__(256, 2) gemm_pipe(
    const float* __restrict__ A, const float* __restrict__ BT,
    float* __restrict__ C, int M, int K, int N,
    const float* __restrict__ bias)
{
    extern __shared__ char smem[];
    pipe_body<RND, false>(smem, A, BT, C, M, K, N, bias);
}

// K and V projections: z picks weight/output; ragged M clamped.
__global__ void __launch_bounds__(256, 2) gemm_pipe_dual(
    const float* __restrict__ A,
    const float* __restrict__ BT0, float* __restrict__ C0,
    const float* __restrict__ BT1, float* __restrict__ C1,
    int M, int K, int N)
{
    extern __shared__ char smem[];
    const float* BT = blockIdx.z ? BT1 : BT0;
    float*       C  = blockIdx.z ? C1 : C0;
    pipe_body<1, true>(smem, A, BT, C, M, K, N, nullptr);
}

// ---------------- weight round+transpose pass ----------------
__global__ void transpose_tf32_kernel(const float* __restrict__ W, float* __restrict__ WT,
                                      int K, int N) {
    __shared__ float tbuf[32][33];
    int k0 = blockIdx.y * 32, n0 = blockIdx.x * 32;
    int x = threadIdx.x, y = threadIdx.y;
#pragma unroll
    for (int i = 0; i < 32; i += 8)
        tbuf[y + i][x] = W[(size_t)(k0 + y + i) * N + n0 + x];
    __syncthreads();
#pragma unroll
    for (int i = 0; i < 32; i += 8)
        WT[(size_t)(n0 + y + i) * K + k0 + x] = rnd_tf32(tbuf[x][y + i]);
}

// ============================================================
// Tensor-core attention (R13 + split waits: V overlaps S phase)
// ============================================================
#define QS_OFF 0
#define KN_OFF 8704
#define VS_OFF 14144
#define ATTN_SMEM ((14144 + 80 * 72) * 4)   // 79616 bytes

__global__ void __launch_bounds__(256, 2) attn_mma(
    const float* __restrict__ q, const float* __restrict__ k,
    const float* __restrict__ v, float* __restrict__ o)
{
    extern __shared__ unsigned sm[];
    const uint32_t sb = smem_u32(sm);
    unsigned* Kn = sm + KN_OFF;
    unsigned* Vs = sm + VS_OFF;

    const int bh = blockIdx.y;
    const int b  = bh >> 4;
    const int h  = bh & 15;
    const int s0 = blockIdx.x * 128;
    const int t  = threadIdx.x;

    if (t < 192) {
        Kn[(77 + (t >> 6)) * 68 + (t & 63)] = 0;
        Vs[(77 + (t >> 6)) * 72 + (t & 63)] = 0;
    }

    // group 0: Q + K
    const float* qbase = q + (size_t)(b * SEQ + s0) * CDIM + h * DHEAD;
#pragma unroll
    for (int i = 0; i < 8; i++) {
        int f = t + i * 256;
        int r = f >> 4, c = f & 15;
        CP16(sb + (QS_OFF + r * 68 + c * 4) * 4, qbase + (size_t)r * CDIM + c * 4);
    }
    const float* kbase = k + (size_t)(b * LTOK) * CDIM + h * DHEAD;
    for (int f = t; f < LTOK * 16; f += 256) {
        int r = f >> 4, c = f & 15;
        CP16(sb + (KN_OFF + r * 68 + c * 4) * 4, kbase + (size_t)r * CDIM + c * 4);
    }
    CP_COMMIT();
    // group 1: V (overlaps S compute)
    const float* vbase = v + (size_t)(b * LTOK) * CDIM + h * DHEAD;
    for (int f = t; f < LTOK * 16; f += 256) {
        int r = f >> 4, c = f & 15;
        CP16(sb + (VS_OFF + r * 72 + c * 4) * 4, vbase + (size_t)r * CDIM + c * 4);
    }
    CP_COMMIT();

    CP_WAIT1();           // Q + K landed
    __syncthreads();

    const int wid = t >> 5, lane = t & 31;
    const int gid = lane >> 2, tg = lane & 3;
    const int wm  = wid * 16;
    const int r0  = wm + gid, r1 = wm + gid + 8;
    const unsigned* Qs = sm + QS_OFF;

    float sacc[10][4];
#pragma unroll
    for (int nf = 0; nf < 10; nf++)
#pragma unroll
        for (int r = 0; r < 4; r++) sacc[nf][r] = 0.f;

#pragma unroll
    for (int kf = 0; kf < 8; kf++) {
        int kk = kf * 8;
        unsigned a0 = Qs[r0 * 68 + kk + tg];
        unsigned a1 = Qs[r1 * 68 + kk + tg];
        unsigned a2 = Qs[r0 * 68 + kk + tg + 4];
        unsigned a3 = Qs[r1 * 68 + kk + tg + 4];
#pragma unroll
        for (int nf = 0; nf < 10; nf++) {
            unsigned b0 = Kn[(nf * 8 + gid) * 68 + kk + tg];
            unsigned b1 = Kn[(nf * 8 + gid) * 68 + kk + tg + 4];
            mma8(sacc[nf], a0, a1, a2, a3, b0, b1);
        }
    }

    const float scale = 0.125f;
    float sum0 = 0.f, sum1 = 0.f;
#pragma unroll
    for (int nf = 0; nf < 10; nf++) {
        int col = nf * 8 + tg * 2;
        float e00 = (col     < LTOK) ? rnd_tf32(__expf(sacc[nf][0] * scale)) : 0.f;
        float e01 = (col + 1 < LTOK) ? rnd_tf32(__expf(sacc[nf][1] * scale)) : 0.f;
        float e10 = (col     < LTOK) ? rnd_tf32(__expf(sacc[nf][2] * scale)) : 0.f;
        float e11 = (col + 1 < LTOK) ? rnd_tf32(__expf(sacc[nf][3] * scale)) : 0.f;
        sum0 += e00 + e01;
        sum1 += e10 + e11;
        sacc[nf][0] = e00; sacc[nf][1] = e01;
        sacc[nf][2] = e10; sacc[nf][3] = e11;
    }
    sum0 += __shfl_xor_sync(0xffffffffu, sum0, 1);
    sum0 += __shfl_xor_sync(0xffffffffu, sum0, 2);
    sum1 += __shfl_xor_sync(0xffffffffu, sum1, 1);
    sum1 += __shfl_xor_sync(0xffffffffu, sum1, 2);
    const float inv0 = 1.0f / sum0;
    const float inv1 = 1.0f / sum1;

    CP_WAIT0();           // V landed
    __syncthreads();

    float oacc[8][4];
#pragma unroll
    for (int nf = 0; nf < 8; nf++)
#pragma unroll
        for (int r = 0; r < 4; r++) oacc[nf][r] = 0.f;

    const int qbse = lane & 28;
    const int src1 = qbse | (tg >> 1);
    const int src2 = qbse | ((tg >> 1) + 2);
    const bool odd = tg & 1;

#pragma unroll
    for (int kf = 0; kf < 10; kf++) {
        float s00 = __shfl_sync(0xffffffffu, sacc[kf][0], src1);
        float s01 = __shfl_sync(0xffffffffu, sacc[kf][1], src1);
        float s10 = __shfl_sync(0xffffffffu, sacc[kf][2], src1);
        float s11 = __shfl_sync(0xffffffffu, sacc[kf][3], src1);
        float t00 = __shfl_sync(0xffffffffu, sacc[kf][0], src2);
        float t01 = __shfl_sync(0xffffffffu, sacc[kf][1], src2);
        float t10 = __shfl_sync(0xffffffffu, sacc[kf][2], src2);
        float t11 = __shfl_sync(0xffffffffu, sacc[kf][3], src2);
        unsigned a0 = __float_as_uint(odd ? s01 : s00);
        unsigned a1 = __float_as_uint(odd ? s11 : s10);
        unsigned a2 = __float_as_uint(odd ? t01 : t00);
        unsigned a3 = __float_as_uint(odd ? t11 : t10);
        int kk = kf * 8;
#pragma unroll
        for (int nf = 0; nf < 8; nf++) {
            unsigned b0 = Vs[(kk + tg) * 72 + nf * 8 + gid];
            unsigned b1 = Vs[(kk + tg + 4) * 72 + nf * 8 + gid];
            mma8(oacc[nf], a0, a1, a2, a3, b0, b1);
        }
    }

    float* ob0 = o + (size_t)(b * SEQ + s0 + r0) * CDIM + h * DHEAD;
    float* ob1 = o + (size_t)(b * SEQ + s0 + r1) * CDIM + h * DHEAD;
#pragma unroll
    for (int nf = 0; nf < 8; nf++) {
        int col = nf * 8 + tg * 2;
        *(float2*)(ob0 + col) = make_float2(rnd_tf32(oacc[nf][0] * inv0),
                                            rnd_tf32(oacc[nf][1] * inv0));
        *(float2*)(ob1 + col) = make_float2(rnd_tf32(oacc[nf][2] * inv1),
                                            rnd_tf32(oacc[nf][3] * inv1));
    }
}

// ============================================================
// launch
// ============================================================
extern "C" void kernel_launch(void* const* d_in, const int* in_sizes, int n_in,
                              void* d_out, int out_size)
{
    const float* hs  = (const float*)d_in[0];
    const float* enc = (const float*)d_in[1];
    const float* Wq  = (const float*)d_in[2];
    const float* Wk  = (const float*)d_in[3];
    const float* Wv  = (const float*)d_in[4];
    const float* Wo  = (const float*)d_in[5];
    const float* bo  = (const float*)d_in[6];
    float* out = (float*)d_out;
    (void)in_sizes; (void)n_in; (void)out_size;

    float *qb, *kb, *vb, *ab, *wqt, *wot, *wkt, *wvt;
    cudaGetSymbolAddress((void**)&qb,  g_q);
    cudaGetSymbolAddress((void**)&kb,  g_k);
    cudaGetSymbolAddress((void**)&vb,  g_v);
    cudaGetSymbolAddress((void**)&ab,  g_attn);
    cudaGetSymbolAddress((void**)&wqt, g_wqt);
    cudaGetSymbolAddress((void**)&wot, g_wot);
    cudaGetSymbolAddress((void**)&wkt, g_wkt);
    cudaGetSymbolAddress((void**)&wvt, g_wvt);

    // round+transpose all weights for the B operand
    transpose_tf32_kernel<<<dim3(CDIM / 32, CDIM / 32), dim3(32, 8)>>>(Wq, wqt, CDIM, CDIM);
    transpose_tf32_kernel<<<dim3(CDIM / 32, CDIM / 32), dim3(32, 8)>>>(Wo, wot, CDIM, CDIM);
    transpose_tf32_kernel<<<dim3(CDIM / 32, CENC / 32), dim3(32, 8)>>>(Wk, wkt, CENC, CDIM);
    transpose_tf32_kernel<<<dim3(CDIM / 32, CENC / 32), dim3(32, 8)>>>(Wv, wvt, CENC, CDIM);

    cudaFuncSetAttribute(gemm_pipe<0>, cudaFuncAttributeMaxDynamicSharedMemorySize, PIPE_SMEM);
    cudaFuncSetAttribute(gemm_pipe<1>, cudaFuncAttributeMaxDynamicSharedMemorySize, PIPE_SMEM);
    cudaFuncSetAttribute(gemm_pipe_dual, cudaFuncAttributeMaxDynamicSharedMemorySize, PIPE_SMEM);

    // q = hs @ Wq  (rounded output -> attn consumes raw bits)
    gemm_pipe<1><<<dim3(CDIM / 128, MQ / 128), 256, PIPE_SMEM>>>(hs, wqt, qb, MQ, CDIM, CDIM, nullptr);

    // k,v = enc @ {Wk,Wv}  (pipelined, ragged M clamped, rounded outputs)
    gemm_pipe_dual<<<dim3(CDIM / 128, (MKV + 127) / 128, 2), 256, PIPE_SMEM>>>(
        enc, wkt, kb, wvt, vb, MKV, CENC, CDIM);

    // tensor-core attention (split-wait staging)
    cudaFuncSetAttribute(attn_mma, cudaFuncAttributeMaxDynamicSharedMemorySize, ATTN_SMEM);
    attn_mma<<<dim3(SEQ / 128, BATCH * NHEAD), 256, ATTN_SMEM>>>(qb, kb, vb, ab);

    // out = attn @ Wo + bo  (raw fp32 output)
    gemm_pipe<0><<<dim3(CDIM / 128, MQ / 128), 256, PIPE_SMEM>>>(ab, wot, out, MQ, CDIM, CDIM, bo);
}